// round 1
// baseline (speedup 1.0000x reference)
#include <cuda_runtime.h>
#include <cstdint>

#define B_   4
#define S_   2048
#define E_   512
#define H_   8
#define D_   64
#define BH_  (B_ * H_)      // 32
#define MTOT (B_ * S_)      // 8192

// scale = E**-0.5; scores are DIVIDED by it => multiply by sqrt(512)
#define SCORE_SCALE 22.62741699796952f

// -------------------- scratch (device globals, no allocs) --------------------
__device__ float g_Q[BH_ * S_ * D_];              // 16 MB
__device__ float g_K[BH_ * S_ * D_];              // 16 MB
__device__ float g_V[BH_ * S_ * D_];              // 16 MB
__device__ float g_O[BH_ * S_ * D_];              // 16 MB
__device__ float g_S[(size_t)BH_ * S_ * S_];      // 512 MB score/prob scratch

// ============================================================================
// Kernel 1: QKV projection.  C[m,n] = sum_k X[m,k] * W_qkv[n,k] + b_qkv[n]
// M=8192, N=1536, K=512. Epilogue scatters into Q/K/V [B,H,S,d].
// Tile 128x128x16, 256 threads, 8x8 per thread.
// ============================================================================
__global__ __launch_bounds__(256) void qkv_gemm(const float* __restrict__ X,
                                                const float* __restrict__ W,
                                                const float* __restrict__ bias) {
    __shared__ __align__(16) float As[16][128];
    __shared__ __align__(16) float Bs[16][128];
    const int tid = threadIdx.x;
    const int m0 = blockIdx.y * 128;
    const int n0 = blockIdx.x * 128;
    const int tm = tid >> 4, tn = tid & 15;

    float acc[8][8];
#pragma unroll
    for (int i = 0; i < 8; i++)
#pragma unroll
        for (int j = 0; j < 8; j++) acc[i][j] = 0.f;

    for (int k0 = 0; k0 < 512; k0 += 16) {
#pragma unroll
        for (int it = 0; it < 2; ++it) {
            int v = tid + it * 256;      // 0..511
            int row = v >> 2, cv = v & 3;
            float4 a = *(const float4*)(X + (size_t)(m0 + row) * 512 + k0 + cv * 4);
            As[cv * 4 + 0][row] = a.x; As[cv * 4 + 1][row] = a.y;
            As[cv * 4 + 2][row] = a.z; As[cv * 4 + 3][row] = a.w;
            float4 b = *(const float4*)(W + (size_t)(n0 + row) * 512 + k0 + cv * 4);
            Bs[cv * 4 + 0][row] = b.x; Bs[cv * 4 + 1][row] = b.y;
            Bs[cv * 4 + 2][row] = b.z; Bs[cv * 4 + 3][row] = b.w;
        }
        __syncthreads();
#pragma unroll
        for (int k = 0; k < 16; k++) {
            float4 a0 = *(const float4*)&As[k][tm * 8];
            float4 a1 = *(const float4*)&As[k][tm * 8 + 4];
            float4 b0 = *(const float4*)&Bs[k][tn * 8];
            float4 b1 = *(const float4*)&Bs[k][tn * 8 + 4];
            float a[8] = {a0.x, a0.y, a0.z, a0.w, a1.x, a1.y, a1.z, a1.w};
            float b[8] = {b0.x, b0.y, b0.z, b0.w, b1.x, b1.y, b1.z, b1.w};
#pragma unroll
            for (int i = 0; i < 8; i++)
#pragma unroll
                for (int j = 0; j < 8; j++) acc[i][j] += a[i] * b[j];
        }
        __syncthreads();
    }

#pragma unroll
    for (int i = 0; i < 8; i++) {
        int m = m0 + tm * 8 + i;
        int bb = m >> 11;         // batch
        int s = m & 2047;         // seq
#pragma unroll
        for (int j = 0; j < 8; j++) {
            int n = n0 + tn * 8 + j;
            float val = acc[i][j] + bias[n];
            int h = n / 192;
            int r = n - h * 192;  // 0..191: [0,64)=q [64,128)=k [128,192)=v
            float* dst = (r < 64) ? g_Q : (r < 128) ? g_K : g_V;
            int jj = r & 63;
            dst[(((size_t)(bb * H_ + h) * S_ + s) * D_) + jj] = val;
        }
    }
}

// ============================================================================
// Kernel 2: scores S = (Q @ K^T) * SCORE_SCALE per (b,h).
// M=N=2048, K=64. grid (16,16,32). Tile 128x128, full K loop 4x16.
// ============================================================================
__global__ __launch_bounds__(256) void score_gemm() {
    __shared__ __align__(16) float As[16][128];
    __shared__ __align__(16) float Bs[16][128];
    const int tid = threadIdx.x;
    const int bh = blockIdx.z;
    const int m0 = blockIdx.y * 128;
    const int n0 = blockIdx.x * 128;
    const int tm = tid >> 4, tn = tid & 15;
    const float* Qp = g_Q + (size_t)bh * S_ * D_;
    const float* Kp = g_K + (size_t)bh * S_ * D_;

    float acc[8][8];
#pragma unroll
    for (int i = 0; i < 8; i++)
#pragma unroll
        for (int j = 0; j < 8; j++) acc[i][j] = 0.f;

    for (int k0 = 0; k0 < 64; k0 += 16) {
#pragma unroll
        for (int it = 0; it < 2; ++it) {
            int v = tid + it * 256;
            int row = v >> 2, cv = v & 3;
            float4 a = *(const float4*)(Qp + (size_t)(m0 + row) * 64 + k0 + cv * 4);
            As[cv * 4 + 0][row] = a.x; As[cv * 4 + 1][row] = a.y;
            As[cv * 4 + 2][row] = a.z; As[cv * 4 + 3][row] = a.w;
            float4 b = *(const float4*)(Kp + (size_t)(n0 + row) * 64 + k0 + cv * 4);
            Bs[cv * 4 + 0][row] = b.x; Bs[cv * 4 + 1][row] = b.y;
            Bs[cv * 4 + 2][row] = b.z; Bs[cv * 4 + 3][row] = b.w;
        }
        __syncthreads();
#pragma unroll
        for (int k = 0; k < 16; k++) {
            float4 a0 = *(const float4*)&As[k][tm * 8];
            float4 a1 = *(const float4*)&As[k][tm * 8 + 4];
            float4 b0 = *(const float4*)&Bs[k][tn * 8];
            float4 b1 = *(const float4*)&Bs[k][tn * 8 + 4];
            float a[8] = {a0.x, a0.y, a0.z, a0.w, a1.x, a1.y, a1.z, a1.w};
            float b[8] = {b0.x, b0.y, b0.z, b0.w, b1.x, b1.y, b1.z, b1.w};
#pragma unroll
            for (int i = 0; i < 8; i++)
#pragma unroll
                for (int j = 0; j < 8; j++) acc[i][j] += a[i] * b[j];
        }
        __syncthreads();
    }

    float* Sp = g_S + (size_t)bh * S_ * S_;
#pragma unroll
    for (int i = 0; i < 8; i++) {
        int m = m0 + tm * 8 + i;
#pragma unroll
        for (int j = 0; j < 8; j++) {
            int n = n0 + tn * 8 + j;
            Sp[(size_t)m * S_ + n] = acc[i][j] * SCORE_SCALE;
        }
    }
}

// ============================================================================
// Kernel 3: fused double softmax over each row of g_S (in place).
// One block (256 thr) per row; 8 elems per thread live in registers.
// ============================================================================
__device__ __forceinline__ float blockReduce(float v, bool isMax, float* red, int tid) {
#pragma unroll
    for (int o = 16; o; o >>= 1) {
        float x = __shfl_xor_sync(0xffffffffu, v, o);
        v = isMax ? fmaxf(v, x) : (v + x);
    }
    if ((tid & 31) == 0) red[tid >> 5] = v;
    __syncthreads();
    float out = red[0];
#pragma unroll
    for (int i = 1; i < 8; i++) out = isMax ? fmaxf(out, red[i]) : (out + red[i]);
    __syncthreads();
    return out;
}

__global__ __launch_bounds__(256) void softmax2_kernel() {
    __shared__ float red[8];
    const int tid = threadIdx.x;
    float* p = g_S + (size_t)blockIdx.x * S_;

    float4 v0 = *((const float4*)p + tid);
    float4 v1 = *((const float4*)p + tid + 256);
    float r[8] = {v0.x, v0.y, v0.z, v0.w, v1.x, v1.y, v1.z, v1.w};

    float m = r[0];
#pragma unroll
    for (int i = 1; i < 8; i++) m = fmaxf(m, r[i]);
    m = blockReduce(m, true, red, tid);

    float z = 0.f;
#pragma unroll
    for (int i = 0; i < 8; i++) { r[i] = __expf(r[i] - m); z += r[i]; }
    z = blockReduce(z, false, red, tid);
    float inv = 1.f / z;

    float z2 = 0.f;
#pragma unroll
    for (int i = 0; i < 8; i++) { r[i] = __expf(r[i] * inv); z2 += r[i]; }
    z2 = blockReduce(z2, false, red, tid);
    float inv2 = 1.f / z2;

    v0 = make_float4(r[0] * inv2, r[1] * inv2, r[2] * inv2, r[3] * inv2);
    v1 = make_float4(r[4] * inv2, r[5] * inv2, r[6] * inv2, r[7] * inv2);
    *((float4*)p + tid) = v0;
    *((float4*)p + tid + 256) = v1;
}

// ============================================================================
// Kernel 4: O = P @ V per (b,h). M=2048, N=64, K=2048.
// Tile 128x64x16, 256 threads, 8x4 per thread. grid (16, 32).
// ============================================================================
__global__ __launch_bounds__(256) void av_gemm() {
    __shared__ __align__(16) float As[16][128];
    __shared__ __align__(16) float Bs[16][64];
    const int tid = threadIdx.x;
    const int bh = blockIdx.y;
    const int m0 = blockIdx.x * 128;
    const int tm = tid >> 4, tn = tid & 15;
    const float* P = g_S + (size_t)bh * S_ * S_;
    const float* V = g_V + (size_t)bh * S_ * D_;

    float acc[8][4];
#pragma unroll
    for (int i = 0; i < 8; i++)
#pragma unroll
        for (int j = 0; j < 4; j++) acc[i][j] = 0.f;

    for (int k0 = 0; k0 < 2048; k0 += 16) {
#pragma unroll
        for (int it = 0; it < 2; ++it) {
            int v = tid + it * 256;
            int row = v >> 2, cv = v & 3;
            float4 a = *(const float4*)(P + (size_t)(m0 + row) * 2048 + k0 + cv * 4);
            As[cv * 4 + 0][row] = a.x; As[cv * 4 + 1][row] = a.y;
            As[cv * 4 + 2][row] = a.z; As[cv * 4 + 3][row] = a.w;
        }
        {
            int row = tid >> 4;   // 0..15 (k)
            int cv = tid & 15;    // 0..15 -> col cv*4
            float4 b = *(const float4*)(V + (size_t)(k0 + row) * 64 + cv * 4);
            *(float4*)&Bs[row][cv * 4] = b;
        }
        __syncthreads();
#pragma unroll
        for (int k = 0; k < 16; k++) {
            float4 a0 = *(const float4*)&As[k][tm * 8];
            float4 a1 = *(const float4*)&As[k][tm * 8 + 4];
            float4 b4 = *(const float4*)&Bs[k][tn * 4];
            float a[8] = {a0.x, a0.y, a0.z, a0.w, a1.x, a1.y, a1.z, a1.w};
            float b[4] = {b4.x, b4.y, b4.z, b4.w};
#pragma unroll
            for (int i = 0; i < 8; i++)
#pragma unroll
                for (int j = 0; j < 4; j++) acc[i][j] += a[i] * b[j];
        }
        __syncthreads();
    }

    float* O = g_O + (size_t)bh * S_ * D_;
#pragma unroll
    for (int i = 0; i < 8; i++) {
        int m = m0 + tm * 8 + i;
#pragma unroll
        for (int j = 0; j < 4; j++) O[(size_t)m * 64 + tn * 4 + j] = acc[i][j];
    }
}

// ============================================================================
// Kernel 5: out projection. Y[m,n] = sum_k O'[m,k] * W_out[n,k] + b_out[n]
// O'[m,k] gathers from g_O [B,H,S,d] (k = h*64 + j). M=8192, N=512, K=512.
// ============================================================================
__global__ __launch_bounds__(256) void out_gemm(const float* __restrict__ W,
                                                const float* __restrict__ bias,
                                                float* __restrict__ Y) {
    __shared__ __align__(16) float As[16][128];
    __shared__ __align__(16) float Bs[16][128];
    const int tid = threadIdx.x;
    const int m0 = blockIdx.y * 128;
    const int n0 = blockIdx.x * 128;
    const int tm = tid >> 4, tn = tid & 15;

    float acc[8][8];
#pragma unroll
    for (int i = 0; i < 8; i++)
#pragma unroll
        for (int j = 0; j < 8; j++) acc[i][j] = 0.f;

    for (int k0 = 0; k0 < 512; k0 += 16) {
        const int h = k0 >> 6;
        const int j0 = k0 & 63;
#pragma unroll
        for (int it = 0; it < 2; ++it) {
            int v = tid + it * 256;
            int row = v >> 2, cv = v & 3;
            int m = m0 + row;
            int bb = m >> 11, s = m & 2047;
            float4 a = *(const float4*)(g_O + ((size_t)(bb * H_ + h) * S_ + s) * D_ + j0 + cv * 4);
            As[cv * 4 + 0][row] = a.x; As[cv * 4 + 1][row] = a.y;
            As[cv * 4 + 2][row] = a.z; As[cv * 4 + 3][row] = a.w;
            float4 b = *(const float4*)(W + (size_t)(n0 + row) * 512 + k0 + cv * 4);
            Bs[cv * 4 + 0][row] = b.x; Bs[cv * 4 + 1][row] = b.y;
            Bs[cv * 4 + 2][row] = b.z; Bs[cv * 4 + 3][row] = b.w;
        }
        __syncthreads();
#pragma unroll
        for (int k = 0; k < 16; k++) {
            float4 a0 = *(const float4*)&As[k][tm * 8];
            float4 a1 = *(const float4*)&As[k][tm * 8 + 4];
            float4 b0 = *(const float4*)&Bs[k][tn * 8];
            float4 b1 = *(const float4*)&Bs[k][tn * 8 + 4];
            float a[8] = {a0.x, a0.y, a0.z, a0.w, a1.x, a1.y, a1.z, a1.w};
            float b[8] = {b0.x, b0.y, b0.z, b0.w, b1.x, b1.y, b1.z, b1.w};
#pragma unroll
            for (int i = 0; i < 8; i++)
#pragma unroll
                for (int j = 0; j < 8; j++) acc[i][j] += a[i] * b[j];
        }
        __syncthreads();
    }

#pragma unroll
    for (int i = 0; i < 8; i++) {
        int m = m0 + tm * 8 + i;
#pragma unroll
        for (int j = 0; j < 8; j++) {
            int n = n0 + tn * 8 + j;
            Y[(size_t)m * 512 + n] = acc[i][j] + bias[n];
        }
    }
}

// ============================================================================
extern "C" void kernel_launch(void* const* d_in, const int* in_sizes, int n_in,
                              void* d_out, int out_size) {
    const float* x     = (const float*)d_in[0];  // [B,S,E]
    const float* W_qkv = (const float*)d_in[1];  // [3E, E]
    const float* b_qkv = (const float*)d_in[2];  // [3E]
    const float* W_out = (const float*)d_in[3];  // [E, E]
    const float* b_out = (const float*)d_in[4];  // [E]
    float* out = (float*)d_out;                  // [B,S,E]

    qkv_gemm<<<dim3(12, 64), 256>>>(x, W_qkv, b_qkv);
    score_gemm<<<dim3(16, 16, 32), 256>>>();
    softmax2_kernel<<<BH_ * S_, 256>>>();
    av_gemm<<<dim3(16, 32), 256>>>();
    out_gemm<<<dim3(4, 64), 256>>>(W_out, b_out, out);
}

// round 2
// speedup vs baseline: 1.7860x; 1.7860x over previous
#include <cuda_runtime.h>
#include <cstdint>

#define B_   4
#define S_   2048
#define E_   512
#define H_   8
#define D_   64
#define BH_  (B_ * H_)      // 32
#define MTOT (B_ * S_)      // 8192

// scale = E**-0.5; scores are DIVIDED by it => multiply by sqrt(512)
#define SCORE_SCALE 22.62741699796952f

// -------------------- scratch (device globals, no allocs) --------------------
__device__ float g_Q[BH_ * S_ * D_];              // 16 MB
__device__ float g_K[BH_ * S_ * D_];              // 16 MB
__device__ float g_V[BH_ * S_ * D_];              // 16 MB
__device__ float g_O[BH_ * S_ * D_];              // 16 MB
__device__ float g_S[(size_t)BH_ * S_ * S_];      // 512 MB score/prob scratch

__device__ __forceinline__ uint32_t f2tf32(float x) {
    uint32_t u;
    asm("cvt.rna.tf32.f32 %0, %1;" : "=r"(u) : "f"(x));
    return u;
}

__device__ __forceinline__ void mma_tf32(float* d, const uint32_t* a, const uint32_t* b) {
    asm volatile(
        "mma.sync.aligned.m16n8k8.row.col.f32.tf32.tf32.f32 "
        "{%0,%1,%2,%3},{%4,%5,%6,%7},{%8,%9},{%0,%1,%2,%3};"
        : "+f"(d[0]), "+f"(d[1]), "+f"(d[2]), "+f"(d[3])
        : "r"(a[0]), "r"(a[1]), "r"(a[2]), "r"(a[3]), "r"(b[0]), "r"(b[1]));
}

// ============================================================================
// Kernel 1: QKV projection (fp32 FFMA). C = X @ W_qkv^T + b. Scatter to Q/K/V.
// ============================================================================
__global__ __launch_bounds__(256) void qkv_gemm(const float* __restrict__ X,
                                                const float* __restrict__ W,
                                                const float* __restrict__ bias) {
    __shared__ __align__(16) float As[16][128];
    __shared__ __align__(16) float Bs[16][128];
    const int tid = threadIdx.x;
    const int m0 = blockIdx.y * 128;
    const int n0 = blockIdx.x * 128;
    const int tm = tid >> 4, tn = tid & 15;

    float acc[8][8];
#pragma unroll
    for (int i = 0; i < 8; i++)
#pragma unroll
        for (int j = 0; j < 8; j++) acc[i][j] = 0.f;

    for (int k0 = 0; k0 < 512; k0 += 16) {
#pragma unroll
        for (int it = 0; it < 2; ++it) {
            int v = tid + it * 256;
            int row = v >> 2, cv = v & 3;
            float4 a = *(const float4*)(X + (size_t)(m0 + row) * 512 + k0 + cv * 4);
            As[cv * 4 + 0][row] = a.x; As[cv * 4 + 1][row] = a.y;
            As[cv * 4 + 2][row] = a.z; As[cv * 4 + 3][row] = a.w;
            float4 b = *(const float4*)(W + (size_t)(n0 + row) * 512 + k0 + cv * 4);
            Bs[cv * 4 + 0][row] = b.x; Bs[cv * 4 + 1][row] = b.y;
            Bs[cv * 4 + 2][row] = b.z; Bs[cv * 4 + 3][row] = b.w;
        }
        __syncthreads();
#pragma unroll
        for (int k = 0; k < 16; k++) {
            float4 a0 = *(const float4*)&As[k][tm * 8];
            float4 a1 = *(const float4*)&As[k][tm * 8 + 4];
            float4 b0 = *(const float4*)&Bs[k][tn * 8];
            float4 b1 = *(const float4*)&Bs[k][tn * 8 + 4];
            float a[8] = {a0.x, a0.y, a0.z, a0.w, a1.x, a1.y, a1.z, a1.w};
            float b[8] = {b0.x, b0.y, b0.z, b0.w, b1.x, b1.y, b1.z, b1.w};
#pragma unroll
            for (int i = 0; i < 8; i++)
#pragma unroll
                for (int j = 0; j < 8; j++) acc[i][j] += a[i] * b[j];
        }
        __syncthreads();
    }

#pragma unroll
    for (int i = 0; i < 8; i++) {
        int m = m0 + tm * 8 + i;
        int bb = m >> 11;
        int s = m & 2047;
#pragma unroll
        for (int j = 0; j < 8; j++) {
            int n = n0 + tn * 8 + j;
            float val = acc[i][j] + bias[n];
            int h = n / 192;
            int r = n - h * 192;
            float* dst = (r < 64) ? g_Q : (r < 128) ? g_K : g_V;
            int jj = r & 63;
            dst[(((size_t)(bb * H_ + h) * S_ + s) * D_) + jj] = val;
        }
    }
}

// ============================================================================
// Kernel 2: scores via TF32 tensor cores. S = (Q @ K^T) * SCORE_SCALE per bh.
// Block 128x128, 8 warps (4 in M x 2 in N). Warp tile 32x64.
// K=64 processed as 2 chunks of 32 in smem (stride 36: conflict-free).
// ============================================================================
__global__ __launch_bounds__(256, 2) void score_gemm_tc() {
    __shared__ uint32_t Qs[128][36];
    __shared__ uint32_t Ks[128][36];
    const int tid = threadIdx.x;
    const int warp = tid >> 5, lane = tid & 31;
    const int g = lane >> 2, t = lane & 3;
    const int warpM = warp & 3;   // 0..3 -> 32 rows each
    const int warpN = warp >> 2;  // 0..1 -> 64 cols each
    const int bh = blockIdx.z;
    const int m0 = blockIdx.y * 128;
    const int n0 = blockIdx.x * 128;
    const float* Qp = g_Q + (size_t)bh * S_ * D_;
    const float* Kp = g_K + (size_t)bh * S_ * D_;

    float acc[2][8][4];
#pragma unroll
    for (int i = 0; i < 2; i++)
#pragma unroll
        for (int j = 0; j < 8; j++)
#pragma unroll
            for (int c = 0; c < 4; c++) acc[i][j][c] = 0.f;

#pragma unroll
    for (int kc = 0; kc < 2; kc++) {
        // load 128x32 chunks of Q and K, cvt to tf32
#pragma unroll
        for (int i = 0; i < 4; i++) {
            int idx = tid + i * 256;          // 0..1023 float4s
            int row = idx >> 3;
            int c4 = (idx & 7) * 4;
            float4 q = *(const float4*)(Qp + (size_t)(m0 + row) * 64 + kc * 32 + c4);
            uint4 qu = {f2tf32(q.x), f2tf32(q.y), f2tf32(q.z), f2tf32(q.w)};
            *(uint4*)&Qs[row][c4] = qu;
            float4 k = *(const float4*)(Kp + (size_t)(n0 + row) * 64 + kc * 32 + c4);
            uint4 ku = {f2tf32(k.x), f2tf32(k.y), f2tf32(k.z), f2tf32(k.w)};
            *(uint4*)&Ks[row][c4] = ku;
        }
        __syncthreads();

#pragma unroll
        for (int ks = 0; ks < 4; ks++) {
            const int k8 = ks * 8;
            uint32_t a[2][4];
#pragma unroll
            for (int mt = 0; mt < 2; mt++) {
                int rowA = warpM * 32 + mt * 16;
                a[mt][0] = Qs[rowA + g][k8 + t];
                a[mt][1] = Qs[rowA + g + 8][k8 + t];
                a[mt][2] = Qs[rowA + g][k8 + t + 4];
                a[mt][3] = Qs[rowA + g + 8][k8 + t + 4];
            }
            uint32_t b[8][2];
#pragma unroll
            for (int nt = 0; nt < 8; nt++) {
                int colB = warpN * 64 + nt * 8;
                b[nt][0] = Ks[colB + g][k8 + t];
                b[nt][1] = Ks[colB + g][k8 + t + 4];
            }
#pragma unroll
            for (int mt = 0; mt < 2; mt++)
#pragma unroll
                for (int nt = 0; nt < 8; nt++) mma_tf32(acc[mt][nt], a[mt], b[nt]);
        }
        __syncthreads();
    }

    float* Sp = g_S + (size_t)bh * S_ * S_;
#pragma unroll
    for (int mt = 0; mt < 2; mt++) {
        int m = m0 + warpM * 32 + mt * 16 + g;
#pragma unroll
        for (int nt = 0; nt < 8; nt++) {
            int n = n0 + warpN * 64 + nt * 8 + 2 * t;
            float2 lo = {acc[mt][nt][0] * SCORE_SCALE, acc[mt][nt][1] * SCORE_SCALE};
            float2 hi = {acc[mt][nt][2] * SCORE_SCALE, acc[mt][nt][3] * SCORE_SCALE};
            *(float2*)(Sp + (size_t)m * S_ + n) = lo;
            *(float2*)(Sp + (size_t)(m + 8) * S_ + n) = hi;
        }
    }
}

// ============================================================================
// Kernel 3: fused double softmax over each row of g_S (in place).
// ============================================================================
__device__ __forceinline__ float blockReduce(float v, bool isMax, float* red, int tid) {
#pragma unroll
    for (int o = 16; o; o >>= 1) {
        float x = __shfl_xor_sync(0xffffffffu, v, o);
        v = isMax ? fmaxf(v, x) : (v + x);
    }
    if ((tid & 31) == 0) red[tid >> 5] = v;
    __syncthreads();
    float out = red[0];
#pragma unroll
    for (int i = 1; i < 8; i++) out = isMax ? fmaxf(out, red[i]) : (out + red[i]);
    __syncthreads();
    return out;
}

__global__ __launch_bounds__(256) void softmax2_kernel() {
    __shared__ float red[8];
    const int tid = threadIdx.x;
    float* p = g_S + (size_t)blockIdx.x * S_;

    float4 v0 = *((const float4*)p + tid);
    float4 v1 = *((const float4*)p + tid + 256);
    float r[8] = {v0.x, v0.y, v0.z, v0.w, v1.x, v1.y, v1.z, v1.w};

    float m = r[0];
#pragma unroll
    for (int i = 1; i < 8; i++) m = fmaxf(m, r[i]);
    m = blockReduce(m, true, red, tid);

    float z = 0.f;
#pragma unroll
    for (int i = 0; i < 8; i++) { r[i] = __expf(r[i] - m); z += r[i]; }
    z = blockReduce(z, false, red, tid);
    float inv = 1.f / z;

    float z2 = 0.f;
#pragma unroll
    for (int i = 0; i < 8; i++) { r[i] = __expf(r[i] * inv); z2 += r[i]; }
    z2 = blockReduce(z2, false, red, tid);
    float inv2 = 1.f / z2;

    v0 = make_float4(r[0] * inv2, r[1] * inv2, r[2] * inv2, r[3] * inv2);
    v1 = make_float4(r[4] * inv2, r[5] * inv2, r[6] * inv2, r[7] * inv2);
    *((float4*)p + tid) = v0;
    *((float4*)p + tid + 256) = v1;
}

// ============================================================================
// Kernel 4: O = P @ V via TF32 tensor cores. M=2048, N=64, K=2048 per bh.
// Block 128x64. 8 warps, each 16 rows x 64 cols. K chunks of 32.
// P smem stride 36 (4g+t distinct), V smem stride 72 (8t+g distinct).
// ============================================================================
__global__ __launch_bounds__(256, 2) void av_gemm_tc() {
    __shared__ uint32_t Ps[128][36];
    __shared__ uint32_t Vs[32][72];
    const int tid = threadIdx.x;
    const int warp = tid >> 5, lane = tid & 31;
    const int g = lane >> 2, t = lane & 3;
    const int bh = blockIdx.y;
    const int m0 = blockIdx.x * 128;
    const float* P = g_S + (size_t)bh * S_ * S_;
    const float* V = g_V + (size_t)bh * S_ * D_;

    float acc[8][4];
#pragma unroll
    for (int j = 0; j < 8; j++)
#pragma unroll
        for (int c = 0; c < 4; c++) acc[j][c] = 0.f;

    for (int kc = 0; kc < 64; kc++) {
        // P chunk 128x32 -> 1024 float4s, 4 per thread
#pragma unroll
        for (int i = 0; i < 4; i++) {
            int idx = tid + i * 256;
            int row = idx >> 3;
            int c4 = (idx & 7) * 4;
            float4 p = *(const float4*)(P + (size_t)(m0 + row) * 2048 + kc * 32 + c4);
            uint4 pu = {f2tf32(p.x), f2tf32(p.y), f2tf32(p.z), f2tf32(p.w)};
            *(uint4*)&Ps[row][c4] = pu;
        }
        // V chunk 32x64 -> 512 float4s, 2 per thread
#pragma unroll
        for (int i = 0; i < 2; i++) {
            int idx = tid + i * 256;
            int row = idx >> 4;
            int c4 = (idx & 15) * 4;
            float4 v = *(const float4*)(V + (size_t)(kc * 32 + row) * 64 + c4);
            uint4 vu = {f2tf32(v.x), f2tf32(v.y), f2tf32(v.z), f2tf32(v.w)};
            *(uint4*)&Vs[row][c4] = vu;
        }
        __syncthreads();

#pragma unroll
        for (int ks = 0; ks < 4; ks++) {
            const int k8 = ks * 8;
            uint32_t a[4];
            int rowA = warp * 16;
            a[0] = Ps[rowA + g][k8 + t];
            a[1] = Ps[rowA + g + 8][k8 + t];
            a[2] = Ps[rowA + g][k8 + t + 4];
            a[3] = Ps[rowA + g + 8][k8 + t + 4];
            uint32_t b[8][2];
#pragma unroll
            for (int nt = 0; nt < 8; nt++) {
                b[nt][0] = Vs[k8 + t][nt * 8 + g];
                b[nt][1] = Vs[k8 + t + 4][nt * 8 + g];
            }
#pragma unroll
            for (int nt = 0; nt < 8; nt++) mma_tf32(acc[nt], a, b[nt]);
        }
        __syncthreads();
    }

    float* O = g_O + (size_t)bh * S_ * D_;
    int m = m0 + warp * 16 + g;
#pragma unroll
    for (int nt = 0; nt < 8; nt++) {
        int n = nt * 8 + 2 * t;
        *(float2*)(O + (size_t)m * 64 + n) = make_float2(acc[nt][0], acc[nt][1]);
        *(float2*)(O + (size_t)(m + 8) * 64 + n) = make_float2(acc[nt][2], acc[nt][3]);
    }
}

// ============================================================================
// Kernel 5: out projection (fp32 FFMA). Y = O' @ W_out^T + b.
// ============================================================================
__global__ __launch_bounds__(256) void out_gemm(const float* __restrict__ W,
                                                const float* __restrict__ bias,
                                                float* __restrict__ Y) {
    __shared__ __align__(16) float As[16][128];
    __shared__ __align__(16) float Bs[16][128];
    const int tid = threadIdx.x;
    const int m0 = blockIdx.y * 128;
    const int n0 = blockIdx.x * 128;
    const int tm = tid >> 4, tn = tid & 15;

    float acc[8][8];
#pragma unroll
    for (int i = 0; i < 8; i++)
#pragma unroll
        for (int j = 0; j < 8; j++) acc[i][j] = 0.f;

    for (int k0 = 0; k0 < 512; k0 += 16) {
        const int h = k0 >> 6;
        const int j0 = k0 & 63;
#pragma unroll
        for (int it = 0; it < 2; ++it) {
            int v = tid + it * 256;
            int row = v >> 2, cv = v & 3;
            int m = m0 + row;
            int bb = m >> 11, s = m & 2047;
            float4 a = *(const float4*)(g_O + ((size_t)(bb * H_ + h) * S_ + s) * D_ + j0 + cv * 4);
            As[cv * 4 + 0][row] = a.x; As[cv * 4 + 1][row] = a.y;
            As[cv * 4 + 2][row] = a.z; As[cv * 4 + 3][row] = a.w;
            float4 b = *(const float4*)(W + (size_t)(n0 + row) * 512 + k0 + cv * 4);
            Bs[cv * 4 + 0][row] = b.x; Bs[cv * 4 + 1][row] = b.y;
            Bs[cv * 4 + 2][row] = b.z; Bs[cv * 4 + 3][row] = b.w;
        }
        __syncthreads();
#pragma unroll
        for (int k = 0; k < 16; k++) {
            float4 a0 = *(const float4*)&As[k][tm * 8];
            float4 a1 = *(const float4*)&As[k][tm * 8 + 4];
            float4 b0 = *(const float4*)&Bs[k][tn * 8];
            float4 b1 = *(const float4*)&Bs[k][tn * 8 + 4];
            float a[8] = {a0.x, a0.y, a0.z, a0.w, a1.x, a1.y, a1.z, a1.w};
            float b[8] = {b0.x, b0.y, b0.z, b0.w, b1.x, b1.y, b1.z, b1.w};
#pragma unroll
            for (int i = 0; i < 8; i++)
#pragma unroll
                for (int j = 0; j < 8; j++) acc[i][j] += a[i] * b[j];
        }
        __syncthreads();
    }

#pragma unroll
    for (int i = 0; i < 8; i++) {
        int m = m0 + tm * 8 + i;
#pragma unroll
        for (int j = 0; j < 8; j++) {
            int n = n0 + tn * 8 + j;
            Y[(size_t)m * 512 + n] = acc[i][j] + bias[n];
        }
    }
}

// ============================================================================
extern "C" void kernel_launch(void* const* d_in, const int* in_sizes, int n_in,
                              void* d_out, int out_size) {
    const float* x     = (const float*)d_in[0];  // [B,S,E]
    const float* W_qkv = (const float*)d_in[1];  // [3E, E]
    const float* b_qkv = (const float*)d_in[2];  // [3E]
    const float* W_out = (const float*)d_in[3];  // [E, E]
    const float* b_out = (const float*)d_in[4];  // [E]
    float* out = (float*)d_out;                  // [B,S,E]

    qkv_gemm<<<dim3(12, 64), 256>>>(x, W_qkv, b_qkv);
    score_gemm_tc<<<dim3(16, 16, 32), 256>>>();
    softmax2_kernel<<<BH_ * S_, 256>>>();
    av_gemm_tc<<<dim3(16, 32), 256>>>();
    out_gemm<<<dim3(4, 64), 256>>>(W_out, b_out, out);
}

// round 3
// speedup vs baseline: 2.7683x; 1.5500x over previous
#include <cuda_runtime.h>
#include <cstdint>

#define B_   4
#define S_   2048
#define E_   512
#define H_   8
#define D_   64
#define BH_  (B_ * H_)      // 32

// scale = E**-0.5; scores are DIVIDED by it => multiply by sqrt(512)
#define SCORE_SCALE 22.62741699796952f

// -------------------- scratch (device globals, no allocs) --------------------
__device__ float g_Q[BH_ * S_ * D_];              // 16 MB
__device__ float g_K[BH_ * S_ * D_];              // 16 MB
__device__ float g_V[BH_ * S_ * D_];              // 16 MB
__device__ float g_O[BH_ * S_ * D_];              // 16 MB

__device__ __forceinline__ uint32_t f2tf32(float x) {
    uint32_t u;
    asm("cvt.rna.tf32.f32 %0, %1;" : "=r"(u) : "f"(x));
    return u;
}

__device__ __forceinline__ void mma_tf32(float* d, const uint32_t* a, const uint32_t* b) {
    asm volatile(
        "mma.sync.aligned.m16n8k8.row.col.f32.tf32.tf32.f32 "
        "{%0,%1,%2,%3},{%4,%5,%6,%7},{%8,%9},{%0,%1,%2,%3};"
        : "+f"(d[0]), "+f"(d[1]), "+f"(d[2]), "+f"(d[3])
        : "r"(a[0]), "r"(a[1]), "r"(a[2]), "r"(a[3]), "r"(b[0]), "r"(b[1]));
}

// ============================================================================
// Kernel 1: QKV projection via TF32 MMA. C = X @ W_qkv^T + b, scatter to QKV.
// M=8192, N=1536, K=512. Block 128x128, warps 4(M)x2(N), warp tile 32x64.
// ============================================================================
__global__ __launch_bounds__(256) void qkv_gemm_tc(const float* __restrict__ X,
                                                   const float* __restrict__ W,
                                                   const float* __restrict__ bias) {
    __shared__ uint32_t As[128 * 36];
    __shared__ uint32_t Bs[128 * 36];
    const int tid = threadIdx.x;
    const int warp = tid >> 5, lane = tid & 31;
    const int g = lane >> 2, t = lane & 3;
    const int warpM = warp & 3;
    const int warpN = warp >> 2;
    const int m0 = blockIdx.y * 128;
    const int n0 = blockIdx.x * 128;

    float acc[2][8][4];
#pragma unroll
    for (int i = 0; i < 2; i++)
#pragma unroll
        for (int j = 0; j < 8; j++)
#pragma unroll
            for (int c = 0; c < 4; c++) acc[i][j][c] = 0.f;

    for (int kc = 0; kc < 16; kc++) {
        __syncthreads();
#pragma unroll
        for (int i = 0; i < 4; i++) {
            int idx = tid + i * 256;
            int row = idx >> 3;
            int c4 = (idx & 7) * 4;
            float4 a = *(const float4*)(X + (size_t)(m0 + row) * 512 + kc * 32 + c4);
            As[row * 36 + c4 + 0] = f2tf32(a.x); As[row * 36 + c4 + 1] = f2tf32(a.y);
            As[row * 36 + c4 + 2] = f2tf32(a.z); As[row * 36 + c4 + 3] = f2tf32(a.w);
            float4 b = *(const float4*)(W + (size_t)(n0 + row) * 512 + kc * 32 + c4);
            Bs[row * 36 + c4 + 0] = f2tf32(b.x); Bs[row * 36 + c4 + 1] = f2tf32(b.y);
            Bs[row * 36 + c4 + 2] = f2tf32(b.z); Bs[row * 36 + c4 + 3] = f2tf32(b.w);
        }
        __syncthreads();
#pragma unroll
        for (int ks = 0; ks < 4; ks++) {
            const int k8 = ks * 8;
            uint32_t a[2][4];
#pragma unroll
            for (int mt = 0; mt < 2; mt++) {
                int rowA = warpM * 32 + mt * 16;
                a[mt][0] = As[(rowA + g) * 36 + k8 + t];
                a[mt][1] = As[(rowA + g + 8) * 36 + k8 + t];
                a[mt][2] = As[(rowA + g) * 36 + k8 + t + 4];
                a[mt][3] = As[(rowA + g + 8) * 36 + k8 + t + 4];
            }
#pragma unroll
            for (int nt = 0; nt < 8; nt++) {
                int colB = warpN * 64 + nt * 8;
                uint32_t b[2];
                b[0] = Bs[(colB + g) * 36 + k8 + t];
                b[1] = Bs[(colB + g) * 36 + k8 + t + 4];
#pragma unroll
                for (int mt = 0; mt < 2; mt++) mma_tf32(acc[mt][nt], a[mt], b);
            }
        }
    }

#pragma unroll
    for (int mt = 0; mt < 2; mt++) {
        int m = m0 + warpM * 32 + mt * 16 + g;
        int bb = m >> 11;
        int s = m & 2047;
#pragma unroll
        for (int nt = 0; nt < 8; nt++) {
            int n = n0 + warpN * 64 + nt * 8 + 2 * t;
            int h = n / 192;
            int r = n - h * 192;
            float* dst = (r < 64) ? g_Q : (r < 128) ? g_K : g_V;
            int jj = r & 63;
            float2 lo = {acc[mt][nt][0] + bias[n], acc[mt][nt][1] + bias[n + 1]};
            float2 hi = {acc[mt][nt][2] + bias[n], acc[mt][nt][3] + bias[n + 1]};
            *(float2*)(dst + (((size_t)(bb * H_ + h) * S_ + s) * D_) + jj) = lo;
            *(float2*)(dst + (((size_t)(bb * H_ + h) * S_ + (s + 8)) * D_) + jj) = hi;
        }
    }
}

// ============================================================================
// Kernel 2: fused attention with double softmax (flash-style, 2 passes).
// Per block: (bh, 128 query rows) x all 2048 keys.
// Pass 1: online row max m, z = sum exp(s-m). Pass 2: recompute s,
// u = exp(exp(s-m)/z), O += u @ V, usum += u; final O /= usum.
// 8 warps, each owns 16 rows (S tile rows AND O rows -> P smem warp-private).
// ============================================================================
#define QS_OFF 0
#define KS_OFF (128 * 68)
#define VS_OFF (2 * 128 * 68)
#define PS_OFF (2 * 128 * 68 + 128 * 72)
#define FUSED_SMEM_WORDS (3 * 128 * 68 + 128 * 72)

__global__ __launch_bounds__(256) void fused_attn() {
    extern __shared__ uint32_t sh[];
    uint32_t* Qs = sh + QS_OFF;   // [128][68] tf32, scaled
    uint32_t* Ks = sh + KS_OFF;   // [128][68]
    uint32_t* Vs = sh + VS_OFF;   // [128][72]
    uint32_t* Ps = sh + PS_OFF;   // [128][68] warp-private rows

    const int tid = threadIdx.x;
    const int warp = tid >> 5, lane = tid & 31;
    const int g = lane >> 2, t = lane & 3;
    const int bh = blockIdx.y;
    const int m0 = blockIdx.x * 128;
    const int rowA = warp * 16;
    const float* Qp = g_Q + (size_t)bh * S_ * D_;
    const float* Kp = g_K + (size_t)bh * S_ * D_;
    const float* Vp = g_V + (size_t)bh * S_ * D_;

    // Load Q tile once (SCORE_SCALE folded in)
#pragma unroll
    for (int i = 0; i < 8; i++) {
        int idx = tid + i * 256;
        int row = idx >> 4;
        int c4 = (idx & 15) * 4;
        float4 q = *(const float4*)(Qp + (size_t)(m0 + row) * 64 + c4);
        Qs[row * 68 + c4 + 0] = f2tf32(q.x * SCORE_SCALE);
        Qs[row * 68 + c4 + 1] = f2tf32(q.y * SCORE_SCALE);
        Qs[row * 68 + c4 + 2] = f2tf32(q.z * SCORE_SCALE);
        Qs[row * 68 + c4 + 3] = f2tf32(q.w * SCORE_SCALE);
    }

    float rm[2] = {-3.0e38f, -3.0e38f};
    float rz[2] = {0.f, 0.f};

    // ----------------------------- pass 1 -----------------------------
    for (int kt = 0; kt < 16; kt++) {
        __syncthreads();
#pragma unroll
        for (int i = 0; i < 8; i++) {
            int idx = tid + i * 256;
            int row = idx >> 4;
            int c4 = (idx & 15) * 4;
            float4 k = *(const float4*)(Kp + (size_t)(kt * 128 + row) * 64 + c4);
            Ks[row * 68 + c4 + 0] = f2tf32(k.x); Ks[row * 68 + c4 + 1] = f2tf32(k.y);
            Ks[row * 68 + c4 + 2] = f2tf32(k.z); Ks[row * 68 + c4 + 3] = f2tf32(k.w);
        }
        __syncthreads();

        float acc[16][4];
#pragma unroll
        for (int nt = 0; nt < 16; nt++)
#pragma unroll
            for (int c = 0; c < 4; c++) acc[nt][c] = 0.f;

#pragma unroll
        for (int ks = 0; ks < 8; ks++) {
            const int k8 = ks * 8;
            uint32_t a[4];
            a[0] = Qs[(rowA + g) * 68 + k8 + t];
            a[1] = Qs[(rowA + g + 8) * 68 + k8 + t];
            a[2] = Qs[(rowA + g) * 68 + k8 + t + 4];
            a[3] = Qs[(rowA + g + 8) * 68 + k8 + t + 4];
#pragma unroll
            for (int nt = 0; nt < 16; nt++) {
                uint32_t b[2];
                b[0] = Ks[(nt * 8 + g) * 68 + k8 + t];
                b[1] = Ks[(nt * 8 + g) * 68 + k8 + t + 4];
                mma_tf32(acc[nt], a, b);
            }
        }

        // per-row (g and g+8) stats
        float tmax[2] = {-3.0e38f, -3.0e38f};
#pragma unroll
        for (int nt = 0; nt < 16; nt++) {
            tmax[0] = fmaxf(tmax[0], fmaxf(acc[nt][0], acc[nt][1]));
            tmax[1] = fmaxf(tmax[1], fmaxf(acc[nt][2], acc[nt][3]));
        }
#pragma unroll
        for (int h = 0; h < 2; h++) {
            tmax[h] = fmaxf(tmax[h], __shfl_xor_sync(0xffffffffu, tmax[h], 1));
            tmax[h] = fmaxf(tmax[h], __shfl_xor_sync(0xffffffffu, tmax[h], 2));
            float mnew = fmaxf(rm[h], tmax[h]);
            float ts = 0.f;
#pragma unroll
            for (int nt = 0; nt < 16; nt++) {
                ts += __expf(acc[nt][2 * h] - mnew) + __expf(acc[nt][2 * h + 1] - mnew);
            }
            ts += __shfl_xor_sync(0xffffffffu, ts, 1);
            ts += __shfl_xor_sync(0xffffffffu, ts, 2);
            rz[h] = rz[h] * __expf(rm[h] - mnew) + ts;
            rm[h] = mnew;
        }
    }

    float zinv[2] = {1.f / rz[0], 1.f / rz[1]};
    float usum[2] = {0.f, 0.f};
    float acco[8][4];
#pragma unroll
    for (int nt = 0; nt < 8; nt++)
#pragma unroll
        for (int c = 0; c < 4; c++) acco[nt][c] = 0.f;

    // ----------------------------- pass 2 -----------------------------
    for (int kt = 0; kt < 16; kt++) {
        __syncthreads();
#pragma unroll
        for (int i = 0; i < 8; i++) {
            int idx = tid + i * 256;
            int row = idx >> 4;
            int c4 = (idx & 15) * 4;
            float4 k = *(const float4*)(Kp + (size_t)(kt * 128 + row) * 64 + c4);
            Ks[row * 68 + c4 + 0] = f2tf32(k.x); Ks[row * 68 + c4 + 1] = f2tf32(k.y);
            Ks[row * 68 + c4 + 2] = f2tf32(k.z); Ks[row * 68 + c4 + 3] = f2tf32(k.w);
            float4 v = *(const float4*)(Vp + (size_t)(kt * 128 + row) * 64 + c4);
            Vs[row * 72 + c4 + 0] = f2tf32(v.x); Vs[row * 72 + c4 + 1] = f2tf32(v.y);
            Vs[row * 72 + c4 + 2] = f2tf32(v.z); Vs[row * 72 + c4 + 3] = f2tf32(v.w);
        }
        __syncthreads();

        float acc[16][4];
#pragma unroll
        for (int nt = 0; nt < 16; nt++)
#pragma unroll
            for (int c = 0; c < 4; c++) acc[nt][c] = 0.f;

#pragma unroll
        for (int ks = 0; ks < 8; ks++) {
            const int k8 = ks * 8;
            uint32_t a[4];
            a[0] = Qs[(rowA + g) * 68 + k8 + t];
            a[1] = Qs[(rowA + g + 8) * 68 + k8 + t];
            a[2] = Qs[(rowA + g) * 68 + k8 + t + 4];
            a[3] = Qs[(rowA + g + 8) * 68 + k8 + t + 4];
#pragma unroll
            for (int nt = 0; nt < 16; nt++) {
                uint32_t b[2];
                b[0] = Ks[(nt * 8 + g) * 68 + k8 + t];
                b[1] = Ks[(nt * 8 + g) * 68 + k8 + t + 4];
                mma_tf32(acc[nt], a, b);
            }
        }

        // u = exp(exp(s - m)/z); PV MMA in two 64-key halves through
        // warp-private Ps rows (this warp's S rows == its O rows).
#pragma unroll
        for (int half = 0; half < 2; half++) {
#pragma unroll
            for (int nt2 = 0; nt2 < 8; nt2++) {
                int nt = half * 8 + nt2;
                float u0 = __expf(__expf(acc[nt][0] - rm[0]) * zinv[0]);
                float u1 = __expf(__expf(acc[nt][1] - rm[0]) * zinv[0]);
                float u2 = __expf(__expf(acc[nt][2] - rm[1]) * zinv[1]);
                float u3 = __expf(__expf(acc[nt][3] - rm[1]) * zinv[1]);
                uint32_t w0 = f2tf32(u0), w1 = f2tf32(u1);
                uint32_t w2 = f2tf32(u2), w3 = f2tf32(u3);
                // usum from the tf32-rounded values (exactly what PV MMA sees)
                usum[0] += __uint_as_float(w0) + __uint_as_float(w1);
                usum[1] += __uint_as_float(w2) + __uint_as_float(w3);
                Ps[(rowA + g) * 68 + nt2 * 8 + 2 * t] = w0;
                Ps[(rowA + g) * 68 + nt2 * 8 + 2 * t + 1] = w1;
                Ps[(rowA + g + 8) * 68 + nt2 * 8 + 2 * t] = w2;
                Ps[(rowA + g + 8) * 68 + nt2 * 8 + 2 * t + 1] = w3;
            }
            __syncwarp();
#pragma unroll
            for (int ks = 0; ks < 8; ks++) {
                const int k8 = ks * 8;
                uint32_t a[4];
                a[0] = Ps[(rowA + g) * 68 + k8 + t];
                a[1] = Ps[(rowA + g + 8) * 68 + k8 + t];
                a[2] = Ps[(rowA + g) * 68 + k8 + t + 4];
                a[3] = Ps[(rowA + g + 8) * 68 + k8 + t + 4];
                const int vr = half * 64 + k8;
#pragma unroll
                for (int nt = 0; nt < 8; nt++) {
                    uint32_t b[2];
                    b[0] = Vs[(vr + t) * 72 + nt * 8 + g];
                    b[1] = Vs[(vr + t + 4) * 72 + nt * 8 + g];
                    mma_tf32(acco[nt], a, b);
                }
            }
            __syncwarp();
        }
    }

    // finalize: O row /= usum row
    usum[0] += __shfl_xor_sync(0xffffffffu, usum[0], 1);
    usum[0] += __shfl_xor_sync(0xffffffffu, usum[0], 2);
    usum[1] += __shfl_xor_sync(0xffffffffu, usum[1], 1);
    usum[1] += __shfl_xor_sync(0xffffffffu, usum[1], 2);
    float oinv0 = 1.f / usum[0];
    float oinv1 = 1.f / usum[1];

    float* O = g_O + (size_t)bh * S_ * D_;
    int m = m0 + rowA + g;
#pragma unroll
    for (int nt = 0; nt < 8; nt++) {
        int n = nt * 8 + 2 * t;
        *(float2*)(O + (size_t)m * 64 + n) =
            make_float2(acco[nt][0] * oinv0, acco[nt][1] * oinv0);
        *(float2*)(O + (size_t)(m + 8) * 64 + n) =
            make_float2(acco[nt][2] * oinv1, acco[nt][3] * oinv1);
    }
}

// ============================================================================
// Kernel 3: out projection via TF32 MMA. Y = O' @ W_out^T + b.
// M=8192, N=512, K=512. A gathered from g_O [B,H,S,d].
// ============================================================================
__global__ __launch_bounds__(256) void out_gemm_tc(const float* __restrict__ W,
                                                   const float* __restrict__ bias,
                                                   float* __restrict__ Y) {
    __shared__ uint32_t As[128 * 36];
    __shared__ uint32_t Bs[128 * 36];
    const int tid = threadIdx.x;
    const int warp = tid >> 5, lane = tid & 31;
    const int g = lane >> 2, t = lane & 3;
    const int warpM = warp & 3;
    const int warpN = warp >> 2;
    const int m0 = blockIdx.y * 128;
    const int n0 = blockIdx.x * 128;

    float acc[2][8][4];
#pragma unroll
    for (int i = 0; i < 2; i++)
#pragma unroll
        for (int j = 0; j < 8; j++)
#pragma unroll
            for (int c = 0; c < 4; c++) acc[i][j][c] = 0.f;

    for (int kc = 0; kc < 16; kc++) {
        const int h = kc >> 1;
        const int j0 = (kc & 1) * 32;
        __syncthreads();
#pragma unroll
        for (int i = 0; i < 4; i++) {
            int idx = tid + i * 256;
            int row = idx >> 3;
            int c4 = (idx & 7) * 4;
            int mrow = m0 + row;
            int bb = mrow >> 11, s = mrow & 2047;
            float4 a = *(const float4*)(g_O + ((size_t)(bb * H_ + h) * S_ + s) * D_ + j0 + c4);
            As[row * 36 + c4 + 0] = f2tf32(a.x); As[row * 36 + c4 + 1] = f2tf32(a.y);
            As[row * 36 + c4 + 2] = f2tf32(a.z); As[row * 36 + c4 + 3] = f2tf32(a.w);
            float4 b = *(const float4*)(W + (size_t)(n0 + row) * 512 + kc * 32 + c4);
            Bs[row * 36 + c4 + 0] = f2tf32(b.x); Bs[row * 36 + c4 + 1] = f2tf32(b.y);
            Bs[row * 36 + c4 + 2] = f2tf32(b.z); Bs[row * 36 + c4 + 3] = f2tf32(b.w);
        }
        __syncthreads();
#pragma unroll
        for (int ks = 0; ks < 4; ks++) {
            const int k8 = ks * 8;
            uint32_t a[2][4];
#pragma unroll
            for (int mt = 0; mt < 2; mt++) {
                int rowA = warpM * 32 + mt * 16;
                a[mt][0] = As[(rowA + g) * 36 + k8 + t];
                a[mt][1] = As[(rowA + g + 8) * 36 + k8 + t];
                a[mt][2] = As[(rowA + g) * 36 + k8 + t + 4];
                a[mt][3] = As[(rowA + g + 8) * 36 + k8 + t + 4];
            }
#pragma unroll
            for (int nt = 0; nt < 8; nt++) {
                int colB = warpN * 64 + nt * 8;
                uint32_t b[2];
                b[0] = Bs[(colB + g) * 36 + k8 + t];
                b[1] = Bs[(colB + g) * 36 + k8 + t + 4];
#pragma unroll
                for (int mt = 0; mt < 2; mt++) mma_tf32(acc[mt][nt], a[mt], b);
            }
        }
    }

#pragma unroll
    for (int mt = 0; mt < 2; mt++) {
        int m = m0 + warpM * 32 + mt * 16 + g;
#pragma unroll
        for (int nt = 0; nt < 8; nt++) {
            int n = n0 + warpN * 64 + nt * 8 + 2 * t;
            float2 lo = {acc[mt][nt][0] + bias[n], acc[mt][nt][1] + bias[n + 1]};
            float2 hi = {acc[mt][nt][2] + bias[n], acc[mt][nt][3] + bias[n + 1]};
            *(float2*)(Y + (size_t)m * 512 + n) = lo;
            *(float2*)(Y + (size_t)(m + 8) * 512 + n) = hi;
        }
    }
}

// ============================================================================
extern "C" void kernel_launch(void* const* d_in, const int* in_sizes, int n_in,
                              void* d_out, int out_size) {
    const float* x     = (const float*)d_in[0];  // [B,S,E]
    const float* W_qkv = (const float*)d_in[1];  // [3E, E]
    const float* b_qkv = (const float*)d_in[2];  // [3E]
    const float* W_out = (const float*)d_in[3];  // [E, E]
    const float* b_out = (const float*)d_in[4];  // [E]
    float* out = (float*)d_out;                  // [B,S,E]

    static const size_t fused_smem = FUSED_SMEM_WORDS * sizeof(uint32_t);  // 141312 B
    cudaFuncSetAttribute(fused_attn, cudaFuncAttributeMaxDynamicSharedMemorySize,
                         (int)fused_smem);

    qkv_gemm_tc<<<dim3(12, 64), 256>>>(x, W_qkv, b_qkv);
    fused_attn<<<dim3(16, 32), 256, fused_smem>>>();
    out_gemm_tc<<<dim3(4, 64), 256>>>(W_out, b_out, out);
}

// round 5
// speedup vs baseline: 3.3711x; 1.2177x over previous
#include <cuda_runtime.h>
#include <cstdint>

#define B_   4
#define S_   2048
#define E_   512
#define H_   8
#define D_   64
#define BH_  (B_ * H_)      // 32

// scale = E**-0.5; scores are DIVIDED by it => multiply by sqrt(512)
#define SCORE_SCALE 22.62741699796952f

// -------------------- scratch (device globals, no allocs) --------------------
__device__ float g_Q[BH_ * S_ * D_];              // 16 MB
__device__ float g_K[BH_ * S_ * D_];              // 16 MB
__device__ float g_V[BH_ * S_ * D_];              // 16 MB
__device__ float g_O[BH_ * S_ * D_];              // 16 MB

__device__ __forceinline__ uint32_t f2tf32(float x) {
    uint32_t u;
    asm("cvt.rna.tf32.f32 %0, %1;" : "=r"(u) : "f"(x));
    return u;
}

__device__ __forceinline__ void mma_tf32(float* d, const uint32_t* a, const uint32_t* b) {
    asm volatile(
        "mma.sync.aligned.m16n8k8.row.col.f32.tf32.tf32.f32 "
        "{%0,%1,%2,%3},{%4,%5,%6,%7},{%8,%9},{%0,%1,%2,%3};"
        : "+f"(d[0]), "+f"(d[1]), "+f"(d[2]), "+f"(d[3])
        : "r"(a[0]), "r"(a[1]), "r"(a[2]), "r"(a[3]), "r"(b[0]), "r"(b[1]));
}

__device__ __forceinline__ void cp16(uint32_t saddr, const void* gptr) {
    asm volatile("cp.async.cg.shared.global [%0], [%1], 16;" :: "r"(saddr), "l"(gptr));
}
#define CP_COMMIT()  asm volatile("cp.async.commit_group;")
#define CP_WAIT1()   asm volatile("cp.async.wait_group 1;")
#define CP_WAIT0()   asm volatile("cp.async.wait_group 0;")

// ============================================================================
// Kernel 1: QKV projection via TF32 MMA. C = X @ W_qkv^T + b, scatter to QKV.
// ============================================================================
__global__ __launch_bounds__(256) void qkv_gemm_tc(const float* __restrict__ X,
                                                   const float* __restrict__ W,
                                                   const float* __restrict__ bias) {
    __shared__ uint32_t As[128 * 36];
    __shared__ uint32_t Bs[128 * 36];
    const int tid = threadIdx.x;
    const int warp = tid >> 5, lane = tid & 31;
    const int g = lane >> 2, t = lane & 3;
    const int warpM = warp & 3;
    const int warpN = warp >> 2;
    const int m0 = blockIdx.y * 128;
    const int n0 = blockIdx.x * 128;

    float acc[2][8][4];
#pragma unroll
    for (int i = 0; i < 2; i++)
#pragma unroll
        for (int j = 0; j < 8; j++)
#pragma unroll
            for (int c = 0; c < 4; c++) acc[i][j][c] = 0.f;

    for (int kc = 0; kc < 16; kc++) {
        __syncthreads();
#pragma unroll
        for (int i = 0; i < 4; i++) {
            int idx = tid + i * 256;
            int row = idx >> 3;
            int c4 = (idx & 7) * 4;
            float4 a = *(const float4*)(X + (size_t)(m0 + row) * 512 + kc * 32 + c4);
            As[row * 36 + c4 + 0] = f2tf32(a.x); As[row * 36 + c4 + 1] = f2tf32(a.y);
            As[row * 36 + c4 + 2] = f2tf32(a.z); As[row * 36 + c4 + 3] = f2tf32(a.w);
            float4 b = *(const float4*)(W + (size_t)(n0 + row) * 512 + kc * 32 + c4);
            Bs[row * 36 + c4 + 0] = f2tf32(b.x); Bs[row * 36 + c4 + 1] = f2tf32(b.y);
            Bs[row * 36 + c4 + 2] = f2tf32(b.z); Bs[row * 36 + c4 + 3] = f2tf32(b.w);
        }
        __syncthreads();
#pragma unroll
        for (int ks = 0; ks < 4; ks++) {
            const int k8 = ks * 8;
            uint32_t a[2][4];
#pragma unroll
            for (int mt = 0; mt < 2; mt++) {
                int rowA = warpM * 32 + mt * 16;
                a[mt][0] = As[(rowA + g) * 36 + k8 + t];
                a[mt][1] = As[(rowA + g + 8) * 36 + k8 + t];
                a[mt][2] = As[(rowA + g) * 36 + k8 + t + 4];
                a[mt][3] = As[(rowA + g + 8) * 36 + k8 + t + 4];
            }
#pragma unroll
            for (int nt = 0; nt < 8; nt++) {
                int colB = warpN * 64 + nt * 8;
                uint32_t b[2];
                b[0] = Bs[(colB + g) * 36 + k8 + t];
                b[1] = Bs[(colB + g) * 36 + k8 + t + 4];
#pragma unroll
                for (int mt = 0; mt < 2; mt++) mma_tf32(acc[mt][nt], a[mt], b);
            }
        }
    }

#pragma unroll
    for (int mt = 0; mt < 2; mt++) {
        int m = m0 + warpM * 32 + mt * 16 + g;
        int bb = m >> 11;
        int s = m & 2047;
#pragma unroll
        for (int nt = 0; nt < 8; nt++) {
            int n = n0 + warpN * 64 + nt * 8 + 2 * t;
            int h = n / 192;
            int r = n - h * 192;
            float* dst = (r < 64) ? g_Q : (r < 128) ? g_K : g_V;
            int jj = r & 63;
            float2 lo = {acc[mt][nt][0] + bias[n], acc[mt][nt][1] + bias[n + 1]};
            float2 hi = {acc[mt][nt][2] + bias[n], acc[mt][nt][3] + bias[n + 1]};
            *(float2*)(dst + (((size_t)(bb * H_ + h) * S_ + s) * D_) + jj) = lo;
            *(float2*)(dst + (((size_t)(bb * H_ + h) * S_ + (s + 8)) * D_) + jj) = hi;
        }
    }
}

// ============================================================================
// Kernel 2: fused double-softmax attention, 2-pass flash-style.
// 64-key tiles, cp.async double-buffered K/V (raw fp32, HW-truncated tf32),
// shuffle-based P transpose (no P smem), 2 blocks/SM.
// smem: Q[128][68] tf32 + K[2][64][68] + V[2][64][72] = 104 KB.
// ============================================================================
#define FUSED_SMEM_WORDS (128 * 68 + 2 * 64 * 68 + 2 * 64 * 72)  // 26624
#define FUSED_SMEM_BYTES (FUSED_SMEM_WORDS * 4)                  // 106496

__global__ __launch_bounds__(256, 2) void fused_attn() {
    extern __shared__ uint32_t sh[];
    uint32_t* Qs = sh;                       // [128][68]
    uint32_t* Ks = sh + 128 * 68;            // [2][64][68]
    uint32_t* Vs = sh + 128 * 68 + 2 * 64 * 68;  // [2][64][72]

    const int tid = threadIdx.x;
    const int warp = tid >> 5, lane = tid & 31;
    const int g = lane >> 2, t = lane & 3;
    const int bh = blockIdx.y;
    const int m0 = blockIdx.x * 128;
    const int rowA = warp * 16;
    const float* Qp = g_Q + (size_t)bh * S_ * D_;
    const float* Kp = g_K + (size_t)bh * S_ * D_;
    const float* Vp = g_V + (size_t)bh * S_ * D_;

    const uint32_t ks_base = (uint32_t)__cvta_generic_to_shared(Ks);
    const uint32_t vs_base = (uint32_t)__cvta_generic_to_shared(Vs);

    // Q tile once: scale folded, rna-converted
#pragma unroll
    for (int i = 0; i < 8; i++) {
        int idx = tid + i * 256;
        int row = idx >> 4;
        int c4 = (idx & 15) * 4;
        float4 q = *(const float4*)(Qp + (size_t)(m0 + row) * 64 + c4);
        Qs[row * 68 + c4 + 0] = f2tf32(q.x * SCORE_SCALE);
        Qs[row * 68 + c4 + 1] = f2tf32(q.y * SCORE_SCALE);
        Qs[row * 68 + c4 + 2] = f2tf32(q.z * SCORE_SCALE);
        Qs[row * 68 + c4 + 3] = f2tf32(q.w * SCORE_SCALE);
    }

    auto loadK = [&](int kt, int buf) {
#pragma unroll
        for (int i = 0; i < 4; i++) {
            int idx = tid + i * 256;
            int r = idx >> 4;
            int c4 = (idx & 15) * 4;
            cp16(ks_base + (uint32_t)(((buf << 6) + r) * 68 + c4) * 4,
                 Kp + (size_t)(kt * 64 + r) * 64 + c4);
        }
    };
    auto loadV = [&](int kt, int buf) {
#pragma unroll
        for (int i = 0; i < 4; i++) {
            int idx = tid + i * 256;
            int r = idx >> 4;
            int c4 = (idx & 15) * 4;
            cp16(vs_base + (uint32_t)(((buf << 6) + r) * 72 + c4) * 4,
                 Vp + (size_t)(kt * 64 + r) * 64 + c4);
        }
    };

    float rm[2] = {-3.0e38f, -3.0e38f};
    float rz[2] = {0.f, 0.f};

    // ----------------------------- pass 1: m, z -----------------------------
    loadK(0, 0);
    CP_COMMIT();
    for (int kt = 0; kt < 32; kt++) {
        const int buf = kt & 1;
        if (kt < 31) {
            loadK(kt + 1, buf ^ 1);
            CP_COMMIT();
            CP_WAIT1();
        } else {
            CP_WAIT0();
        }
        __syncthreads();
        const uint32_t* Kb = Ks + buf * 64 * 68;

        float acc[8][4];
#pragma unroll
        for (int nt = 0; nt < 8; nt++)
#pragma unroll
            for (int c = 0; c < 4; c++) acc[nt][c] = 0.f;

#pragma unroll
        for (int ks = 0; ks < 8; ks++) {
            const int k8 = ks * 8;
            uint32_t a[4];
            a[0] = Qs[(rowA + g) * 68 + k8 + t];
            a[1] = Qs[(rowA + g + 8) * 68 + k8 + t];
            a[2] = Qs[(rowA + g) * 68 + k8 + t + 4];
            a[3] = Qs[(rowA + g + 8) * 68 + k8 + t + 4];
#pragma unroll
            for (int nt = 0; nt < 8; nt++) {
                uint32_t b[2];
                b[0] = Kb[(nt * 8 + g) * 68 + k8 + t];
                b[1] = Kb[(nt * 8 + g) * 68 + k8 + t + 4];
                mma_tf32(acc[nt], a, b);
            }
        }

        float tmax[2] = {-3.0e38f, -3.0e38f};
#pragma unroll
        for (int nt = 0; nt < 8; nt++) {
            tmax[0] = fmaxf(tmax[0], fmaxf(acc[nt][0], acc[nt][1]));
            tmax[1] = fmaxf(tmax[1], fmaxf(acc[nt][2], acc[nt][3]));
        }
#pragma unroll
        for (int h = 0; h < 2; h++) {
            tmax[h] = fmaxf(tmax[h], __shfl_xor_sync(0xffffffffu, tmax[h], 1));
            tmax[h] = fmaxf(tmax[h], __shfl_xor_sync(0xffffffffu, tmax[h], 2));
            float mnew = fmaxf(rm[h], tmax[h]);
            float ts = 0.f;
#pragma unroll
            for (int nt = 0; nt < 8; nt++) {
                ts += __expf(acc[nt][2 * h] - mnew) + __expf(acc[nt][2 * h + 1] - mnew);
            }
            ts += __shfl_xor_sync(0xffffffffu, ts, 1);
            ts += __shfl_xor_sync(0xffffffffu, ts, 2);
            rz[h] = rz[h] * __expf(rm[h] - mnew) + ts;
            rm[h] = mnew;
        }
        __syncthreads();
    }

    float zinv[2] = {1.f / rz[0], 1.f / rz[1]};
    float usum[2] = {0.f, 0.f};
    float acco[8][4];
#pragma unroll
    for (int nt = 0; nt < 8; nt++)
#pragma unroll
        for (int c = 0; c < 4; c++) acco[nt][c] = 0.f;

    // -------------------- pass 2: u = exp(exp(s-m)/z); O = u@V --------------
    loadK(0, 0);
    loadV(0, 0);
    CP_COMMIT();
    for (int kt = 0; kt < 32; kt++) {
        const int buf = kt & 1;
        if (kt < 31) {
            loadK(kt + 1, buf ^ 1);
            loadV(kt + 1, buf ^ 1);
            CP_COMMIT();
            CP_WAIT1();
        } else {
            CP_WAIT0();
        }
        __syncthreads();
        const uint32_t* Kb = Ks + buf * 64 * 68;
        const uint32_t* Vb = Vs + buf * 64 * 72;

        float acc[8][4];
#pragma unroll
        for (int nt = 0; nt < 8; nt++)
#pragma unroll
            for (int c = 0; c < 4; c++) acc[nt][c] = 0.f;

#pragma unroll
        for (int ks = 0; ks < 8; ks++) {
            const int k8 = ks * 8;
            uint32_t a[4];
            a[0] = Qs[(rowA + g) * 68 + k8 + t];
            a[1] = Qs[(rowA + g + 8) * 68 + k8 + t];
            a[2] = Qs[(rowA + g) * 68 + k8 + t + 4];
            a[3] = Qs[(rowA + g + 8) * 68 + k8 + t + 4];
#pragma unroll
            for (int nt = 0; nt < 8; nt++) {
                uint32_t b[2];
                b[0] = Kb[(nt * 8 + g) * 68 + k8 + t];
                b[1] = Kb[(nt * 8 + g) * 68 + k8 + t + 4];
                mma_tf32(acc[nt], a, b);
            }
        }

        // per 8-key chunk: u, in-register transpose (shfl), PV MMA
        const int s0 = (lane & 0x1c) | (t >> 1);
        const int s1 = s0 + 2;
        const bool odd = (t & 1);
#pragma unroll
        for (int nt = 0; nt < 8; nt++) {
            float u0 = __expf(__expf(acc[nt][0] - rm[0]) * zinv[0]);
            float u1 = __expf(__expf(acc[nt][1] - rm[0]) * zinv[0]);
            float u2 = __expf(__expf(acc[nt][2] - rm[1]) * zinv[1]);
            float u3 = __expf(__expf(acc[nt][3] - rm[1]) * zinv[1]);
            uint32_t w0 = f2tf32(u0), w1 = f2tf32(u1);
            uint32_t w2 = f2tf32(u2), w3 = f2tf32(u3);
            usum[0] += __uint_as_float(w0) + __uint_as_float(w1);
            usum[1] += __uint_as_float(w2) + __uint_as_float(w3);

            uint32_t d0a = __shfl_sync(0xffffffffu, w0, s0);
            uint32_t d1a = __shfl_sync(0xffffffffu, w1, s0);
            uint32_t d2a = __shfl_sync(0xffffffffu, w2, s0);
            uint32_t d3a = __shfl_sync(0xffffffffu, w3, s0);
            uint32_t d0b = __shfl_sync(0xffffffffu, w0, s1);
            uint32_t d1b = __shfl_sync(0xffffffffu, w1, s1);
            uint32_t d2b = __shfl_sync(0xffffffffu, w2, s1);
            uint32_t d3b = __shfl_sync(0xffffffffu, w3, s1);
            uint32_t a[4];
            a[0] = odd ? d1a : d0a;
            a[1] = odd ? d3a : d2a;
            a[2] = odd ? d1b : d0b;
            a[3] = odd ? d3b : d2b;

#pragma unroll
            for (int dt = 0; dt < 8; dt++) {
                uint32_t b[2];
                b[0] = Vb[(nt * 8 + t) * 72 + dt * 8 + g];
                b[1] = Vb[(nt * 8 + t + 4) * 72 + dt * 8 + g];
                mma_tf32(acco[dt], a, b);
            }
        }
        __syncthreads();
    }

    // finalize: O row /= usum row
    usum[0] += __shfl_xor_sync(0xffffffffu, usum[0], 1);
    usum[0] += __shfl_xor_sync(0xffffffffu, usum[0], 2);
    usum[1] += __shfl_xor_sync(0xffffffffu, usum[1], 1);
    usum[1] += __shfl_xor_sync(0xffffffffu, usum[1], 2);
    float oinv0 = 1.f / usum[0];
    float oinv1 = 1.f / usum[1];

    float* O = g_O + (size_t)bh * S_ * D_;
    int m = m0 + rowA + g;
#pragma unroll
    for (int dt = 0; dt < 8; dt++) {
        int n = dt * 8 + 2 * t;
        *(float2*)(O + (size_t)m * 64 + n) =
            make_float2(acco[dt][0] * oinv0, acco[dt][1] * oinv0);
        *(float2*)(O + (size_t)(m + 8) * 64 + n) =
            make_float2(acco[dt][2] * oinv1, acco[dt][3] * oinv1);
    }
}

// ============================================================================
// Kernel 3: out projection via TF32 MMA. Y = O' @ W_out^T + b.
// ============================================================================
__global__ __launch_bounds__(256) void out_gemm_tc(const float* __restrict__ W,
                                                   const float* __restrict__ bias,
                                                   float* __restrict__ Y) {
    __shared__ uint32_t As[128 * 36];
    __shared__ uint32_t Bs[128 * 36];
    const int tid = threadIdx.x;
    const int warp = tid >> 5, lane = tid & 31;
    const int g = lane >> 2, t = lane & 3;
    const int warpM = warp & 3;
    const int warpN = warp >> 2;
    const int m0 = blockIdx.y * 128;
    const int n0 = blockIdx.x * 128;

    float acc[2][8][4];
#pragma unroll
    for (int i = 0; i < 2; i++)
#pragma unroll
        for (int j = 0; j < 8; j++)
#pragma unroll
            for (int c = 0; c < 4; c++) acc[i][j][c] = 0.f;

    for (int kc = 0; kc < 16; kc++) {
        const int h = kc >> 1;
        const int j0 = (kc & 1) * 32;
        __syncthreads();
#pragma unroll
        for (int i = 0; i < 4; i++) {
            int idx = tid + i * 256;
            int row = idx >> 3;
            int c4 = (idx & 7) * 4;
            int mrow = m0 + row;
            int bb = mrow >> 11, s = mrow & 2047;
            float4 a = *(const float4*)(g_O + ((size_t)(bb * H_ + h) * S_ + s) * D_ + j0 + c4);
            As[row * 36 + c4 + 0] = f2tf32(a.x); As[row * 36 + c4 + 1] = f2tf32(a.y);
            As[row * 36 + c4 + 2] = f2tf32(a.z); As[row * 36 + c4 + 3] = f2tf32(a.w);
            float4 b = *(const float4*)(W + (size_t)(n0 + row) * 512 + kc * 32 + c4);
            Bs[row * 36 + c4 + 0] = f2tf32(b.x); Bs[row * 36 + c4 + 1] = f2tf32(b.y);
            Bs[row * 36 + c4 + 2] = f2tf32(b.z); Bs[row * 36 + c4 + 3] = f2tf32(b.w);
        }
        __syncthreads();
#pragma unroll
        for (int ks = 0; ks < 4; ks++) {
            const int k8 = ks * 8;
            uint32_t a[2][4];
#pragma unroll
            for (int mt = 0; mt < 2; mt++) {
                int rowA = warpM * 32 + mt * 16;
                a[mt][0] = As[(rowA + g) * 36 + k8 + t];
                a[mt][1] = As[(rowA + g + 8) * 36 + k8 + t];
                a[mt][2] = As[(rowA + g) * 36 + k8 + t + 4];
                a[mt][3] = As[(rowA + g + 8) * 36 + k8 + t + 4];
            }
#pragma unroll
            for (int nt = 0; nt < 8; nt++) {
                int colB = warpN * 64 + nt * 8;
                uint32_t b[2];
                b[0] = Bs[(colB + g) * 36 + k8 + t];
                b[1] = Bs[(colB + g) * 36 + k8 + t + 4];
#pragma unroll
                for (int mt = 0; mt < 2; mt++) mma_tf32(acc[mt][nt], a[mt], b);
            }
        }
    }

#pragma unroll
    for (int mt = 0; mt < 2; mt++) {
        int m = m0 + warpM * 32 + mt * 16 + g;
#pragma unroll
        for (int nt = 0; nt < 8; nt++) {
            int n = n0 + warpN * 64 + nt * 8 + 2 * t;
            float2 lo = {acc[mt][nt][0] + bias[n], acc[mt][nt][1] + bias[n + 1]};
            float2 hi = {acc[mt][nt][2] + bias[n], acc[mt][nt][3] + bias[n + 1]};
            *(float2*)(Y + (size_t)m * 512 + n) = lo;
            *(float2*)(Y + (size_t)(m + 8) * 512 + n) = hi;
        }
    }
}

// ============================================================================
extern "C" void kernel_launch(void* const* d_in, const int* in_sizes, int n_in,
                              void* d_out, int out_size) {
    const float* x     = (const float*)d_in[0];  // [B,S,E]
    const float* W_qkv = (const float*)d_in[1];  // [3E, E]
    const float* b_qkv = (const float*)d_in[2];  // [3E]
    const float* W_out = (const float*)d_in[3];  // [E, E]
    const float* b_out = (const float*)d_in[4];  // [E]
    float* out = (float*)d_out;                  // [B,S,E]

    cudaFuncSetAttribute(fused_attn, cudaFuncAttributeMaxDynamicSharedMemorySize,
                         FUSED_SMEM_BYTES);

    qkv_gemm_tc<<<dim3(12, 64), 256>>>(x, W_qkv, b_qkv);
    fused_attn<<<dim3(16, 32), 256, FUSED_SMEM_BYTES>>>();
    out_gemm_tc<<<dim3(4, 64), 256>>>(W_out, b_out, out);
}

// round 10
// speedup vs baseline: 3.6026x; 1.0687x over previous
#include <cuda_runtime.h>
#include <cstdint>

#define B_   4
#define S_   2048
#define E_   512
#define H_   8
#define D_   64
#define BH_  (B_ * H_)      // 32

// scale = E**-0.5; scores are DIVIDED by it => multiply by sqrt(512).
// For the fused kernel we also fold log2(e) so softmax runs in base-2 domain.
#define SCORE_SCALE 22.62741699796952f
#define LOG2E       1.4426950408889634f
#define QSCALE_2    (SCORE_SCALE * LOG2E)

// -------------------- scratch (device globals, no allocs) --------------------
__device__ float g_Q[BH_ * S_ * D_];              // 16 MB
__device__ float g_K[BH_ * S_ * D_];              // 16 MB
__device__ float g_V[BH_ * S_ * D_];              // 16 MB
__device__ float g_O[BH_ * S_ * D_];              // 16 MB

__device__ __forceinline__ uint32_t f2tf32(float x) {
    uint32_t u;
    asm("cvt.rna.tf32.f32 %0, %1;" : "=r"(u) : "f"(x));
    return u;
}

__device__ __forceinline__ float ex2(float x) {
    float r;
    asm("ex2.approx.f32 %0, %1;" : "=f"(r) : "f"(x));
    return r;
}

__device__ __forceinline__ void mma_tf32(float* d, const uint32_t* a, const uint32_t* b) {
    asm volatile(
        "mma.sync.aligned.m16n8k8.row.col.f32.tf32.tf32.f32 "
        "{%0,%1,%2,%3},{%4,%5,%6,%7},{%8,%9},{%0,%1,%2,%3};"
        : "+f"(d[0]), "+f"(d[1]), "+f"(d[2]), "+f"(d[3])
        : "r"(a[0]), "r"(a[1]), "r"(a[2]), "r"(a[3]), "r"(b[0]), "r"(b[1]));
}

__device__ __forceinline__ void cp16(uint32_t saddr, const void* gptr) {
    asm volatile("cp.async.cg.shared.global [%0], [%1], 16;" :: "r"(saddr), "l"(gptr));
}
#define CP_COMMIT()  asm volatile("cp.async.commit_group;")
#define CP_WAIT1()   asm volatile("cp.async.wait_group 1;")
#define CP_WAIT0()   asm volatile("cp.async.wait_group 0;")

// ============================================================================
// Kernel 1: QKV projection via TF32 MMA. C = X @ W_qkv^T + b, scatter to QKV.
// NOTE: must keep cvt.rna loads (no cp.async raw fp32) — double-sided tf32
// truncation bias ≈ -9.8e-4 relative would blow the 1e-3 error budget.
// ============================================================================
__global__ __launch_bounds__(256) void qkv_gemm_tc(const float* __restrict__ X,
                                                   const float* __restrict__ W,
                                                   const float* __restrict__ bias) {
    __shared__ uint32_t As[128 * 36];
    __shared__ uint32_t Bs[128 * 36];
    const int tid = threadIdx.x;
    const int warp = tid >> 5, lane = tid & 31;
    const int g = lane >> 2, t = lane & 3;
    const int warpM = warp & 3;
    const int warpN = warp >> 2;
    const int m0 = blockIdx.y * 128;
    const int n0 = blockIdx.x * 128;

    float acc[2][8][4];
#pragma unroll
    for (int i = 0; i < 2; i++)
#pragma unroll
        for (int j = 0; j < 8; j++)
#pragma unroll
            for (int c = 0; c < 4; c++) acc[i][j][c] = 0.f;

    for (int kc = 0; kc < 16; kc++) {
        __syncthreads();
#pragma unroll
        for (int i = 0; i < 4; i++) {
            int idx = tid + i * 256;
            int row = idx >> 3;
            int c4 = (idx & 7) * 4;
            float4 a = *(const float4*)(X + (size_t)(m0 + row) * 512 + kc * 32 + c4);
            As[row * 36 + c4 + 0] = f2tf32(a.x); As[row * 36 + c4 + 1] = f2tf32(a.y);
            As[row * 36 + c4 + 2] = f2tf32(a.z); As[row * 36 + c4 + 3] = f2tf32(a.w);
            float4 b = *(const float4*)(W + (size_t)(n0 + row) * 512 + kc * 32 + c4);
            Bs[row * 36 + c4 + 0] = f2tf32(b.x); Bs[row * 36 + c4 + 1] = f2tf32(b.y);
            Bs[row * 36 + c4 + 2] = f2tf32(b.z); Bs[row * 36 + c4 + 3] = f2tf32(b.w);
        }
        __syncthreads();
#pragma unroll
        for (int ks = 0; ks < 4; ks++) {
            const int k8 = ks * 8;
            uint32_t a[2][4];
#pragma unroll
            for (int mt = 0; mt < 2; mt++) {
                int rowA = warpM * 32 + mt * 16;
                a[mt][0] = As[(rowA + g) * 36 + k8 + t];
                a[mt][1] = As[(rowA + g + 8) * 36 + k8 + t];
                a[mt][2] = As[(rowA + g) * 36 + k8 + t + 4];
                a[mt][3] = As[(rowA + g + 8) * 36 + k8 + t + 4];
            }
#pragma unroll
            for (int nt = 0; nt < 8; nt++) {
                int colB = warpN * 64 + nt * 8;
                uint32_t b[2];
                b[0] = Bs[(colB + g) * 36 + k8 + t];
                b[1] = Bs[(colB + g) * 36 + k8 + t + 4];
#pragma unroll
                for (int mt = 0; mt < 2; mt++) mma_tf32(acc[mt][nt], a[mt], b);
            }
        }
    }

#pragma unroll
    for (int mt = 0; mt < 2; mt++) {
        int m = m0 + warpM * 32 + mt * 16 + g;
        int bb = m >> 11;
        int s = m & 2047;
#pragma unroll
        for (int nt = 0; nt < 8; nt++) {
            int n = n0 + warpN * 64 + nt * 8 + 2 * t;
            int h = n / 192;
            int r = n - h * 192;
            float* dst = (r < 64) ? g_Q : (r < 128) ? g_K : g_V;
            int jj = r & 63;
            float2 lo = {acc[mt][nt][0] + bias[n], acc[mt][nt][1] + bias[n + 1]};
            float2 hi = {acc[mt][nt][2] + bias[n], acc[mt][nt][3] + bias[n + 1]};
            *(float2*)(dst + (((size_t)(bb * H_ + h) * S_ + s) * D_) + jj) = lo;
            *(float2*)(dst + (((size_t)(bb * H_ + h) * S_ + (s + 8)) * D_) + jj) = hi;
        }
    }
}

// ============================================================================
// Kernel 2: fused double-softmax attention, 2-pass flash-style, base-2 domain.
// 128 threads = 4 warps x 32 query rows (2 m-frags). 32-key tiles, cp.async
// double-buffered K/V (raw fp32 -> HW-truncated tf32). 3 blocks/SM.
// smem: Q[128][68] + K[2][32][68] + V[2][32][72] = 70.7 KB.
// ============================================================================
#define TKEY 32
#define NT_  (TKEY / 8)          // 4 key groups per tile
#define NTILES (S_ / TKEY)       // 64 tiles
#define FUSED_SMEM_WORDS (128 * 68 + 2 * TKEY * 68 + 2 * TKEY * 72)
#define FUSED_SMEM_BYTES (FUSED_SMEM_WORDS * 4)   // 70656

__global__ __launch_bounds__(128, 3) void fused_attn() {
    extern __shared__ uint32_t sh[];
    uint32_t* Qs = sh;                              // [128][68]
    uint32_t* Ks = sh + 128 * 68;                   // [2][32][68]
    uint32_t* Vs = sh + 128 * 68 + 2 * TKEY * 68;   // [2][32][72]

    const int tid = threadIdx.x;
    const int warp = tid >> 5, lane = tid & 31;
    const int g = lane >> 2, t = lane & 3;
    const int bh = blockIdx.y;
    const int m0 = blockIdx.x * 128;
    const int rowA = warp * 32;                     // 32 rows per warp
    const float* Qp = g_Q + (size_t)bh * S_ * D_;
    const float* Kp = g_K + (size_t)bh * S_ * D_;
    const float* Vp = g_V + (size_t)bh * S_ * D_;

    const uint32_t ks_base = (uint32_t)__cvta_generic_to_shared(Ks);
    const uint32_t vs_base = (uint32_t)__cvta_generic_to_shared(Vs);

    // Q tile once: base-2 scale folded, rna-converted. 2048 float4 / 128 thr.
#pragma unroll
    for (int i = 0; i < 16; i++) {
        int idx = tid + i * 128;
        int row = idx >> 4;
        int c4 = (idx & 15) * 4;
        float4 q = *(const float4*)(Qp + (size_t)(m0 + row) * 64 + c4);
        Qs[row * 68 + c4 + 0] = f2tf32(q.x * QSCALE_2);
        Qs[row * 68 + c4 + 1] = f2tf32(q.y * QSCALE_2);
        Qs[row * 68 + c4 + 2] = f2tf32(q.z * QSCALE_2);
        Qs[row * 68 + c4 + 3] = f2tf32(q.w * QSCALE_2);
    }

    auto loadK = [&](int kt, int buf) {
#pragma unroll
        for (int i = 0; i < 4; i++) {
            int idx = tid + i * 128;
            int r = idx >> 4;
            int c4 = (idx & 15) * 4;
            cp16(ks_base + (uint32_t)((buf * TKEY + r) * 68 + c4) * 4,
                 Kp + (size_t)(kt * TKEY + r) * 64 + c4);
        }
    };
    auto loadV = [&](int kt, int buf) {
#pragma unroll
        for (int i = 0; i < 4; i++) {
            int idx = tid + i * 128;
            int r = idx >> 4;
            int c4 = (idx & 15) * 4;
            cp16(vs_base + (uint32_t)((buf * TKEY + r) * 72 + c4) * 4,
                 Vp + (size_t)(kt * TKEY + r) * 64 + c4);
        }
    };

    // stats per m-frag (mt) per row-half (h: g / g+8), base-2 domain
    float rm[2][2] = {{-3.0e38f, -3.0e38f}, {-3.0e38f, -3.0e38f}};
    float rz[2][2] = {{0.f, 0.f}, {0.f, 0.f}};

    // ----------------------------- pass 1: m, z -----------------------------
    loadK(0, 0);
    CP_COMMIT();
    for (int kt = 0; kt < NTILES; kt++) {
        const int buf = kt & 1;
        if (kt < NTILES - 1) {
            loadK(kt + 1, buf ^ 1);
            CP_COMMIT();
            CP_WAIT1();
        } else {
            CP_WAIT0();
        }
        __syncthreads();
        const uint32_t* Kb = Ks + buf * TKEY * 68;

        float acc[2][NT_][4];
#pragma unroll
        for (int mt = 0; mt < 2; mt++)
#pragma unroll
            for (int nt = 0; nt < NT_; nt++)
#pragma unroll
                for (int c = 0; c < 4; c++) acc[mt][nt][c] = 0.f;

#pragma unroll
        for (int ks = 0; ks < 8; ks++) {
            const int k8 = ks * 8;
            uint32_t a[2][4];
#pragma unroll
            for (int mt = 0; mt < 2; mt++) {
                int r = rowA + mt * 16;
                a[mt][0] = Qs[(r + g) * 68 + k8 + t];
                a[mt][1] = Qs[(r + g + 8) * 68 + k8 + t];
                a[mt][2] = Qs[(r + g) * 68 + k8 + t + 4];
                a[mt][3] = Qs[(r + g + 8) * 68 + k8 + t + 4];
            }
#pragma unroll
            for (int nt = 0; nt < NT_; nt++) {
                uint32_t b[2];
                b[0] = Kb[(nt * 8 + g) * 68 + k8 + t];
                b[1] = Kb[(nt * 8 + g) * 68 + k8 + t + 4];
#pragma unroll
                for (int mt = 0; mt < 2; mt++) mma_tf32(acc[mt][nt], a[mt], b);
            }
        }

#pragma unroll
        for (int mt = 0; mt < 2; mt++) {
            float tmax[2] = {-3.0e38f, -3.0e38f};
#pragma unroll
            for (int nt = 0; nt < NT_; nt++) {
                tmax[0] = fmaxf(tmax[0], fmaxf(acc[mt][nt][0], acc[mt][nt][1]));
                tmax[1] = fmaxf(tmax[1], fmaxf(acc[mt][nt][2], acc[mt][nt][3]));
            }
#pragma unroll
            for (int h = 0; h < 2; h++) {
                tmax[h] = fmaxf(tmax[h], __shfl_xor_sync(0xffffffffu, tmax[h], 1));
                tmax[h] = fmaxf(tmax[h], __shfl_xor_sync(0xffffffffu, tmax[h], 2));
                float mnew = fmaxf(rm[mt][h], tmax[h]);
                float ts = 0.f;
#pragma unroll
                for (int nt = 0; nt < NT_; nt++) {
                    ts += ex2(acc[mt][nt][2 * h] - mnew) + ex2(acc[mt][nt][2 * h + 1] - mnew);
                }
                ts += __shfl_xor_sync(0xffffffffu, ts, 1);
                ts += __shfl_xor_sync(0xffffffffu, ts, 2);
                rz[mt][h] = rz[mt][h] * ex2(rm[mt][h] - mnew) + ts;
                rm[mt][h] = mnew;
            }
        }
        __syncthreads();
    }

    // zl = (1/z) * log2(e): u = exp(p) = 2^(p*log2e), p = 2^(s'-m') / z
    float zl[2][2];
#pragma unroll
    for (int mt = 0; mt < 2; mt++)
#pragma unroll
        for (int h = 0; h < 2; h++) zl[mt][h] = LOG2E / rz[mt][h];

    float usum[2][2] = {{0.f, 0.f}, {0.f, 0.f}};
    float acco[2][8][4];
#pragma unroll
    for (int mt = 0; mt < 2; mt++)
#pragma unroll
        for (int dt = 0; dt < 8; dt++)
#pragma unroll
            for (int c = 0; c < 4; c++) acco[mt][dt][c] = 0.f;

    // -------------------- pass 2: u = 2^(2^(s'-m')*zl); O = u@V -------------
    loadK(0, 0);
    loadV(0, 0);
    CP_COMMIT();
    for (int kt = 0; kt < NTILES; kt++) {
        const int buf = kt & 1;
        if (kt < NTILES - 1) {
            loadK(kt + 1, buf ^ 1);
            loadV(kt + 1, buf ^ 1);
            CP_COMMIT();
            CP_WAIT1();
        } else {
            CP_WAIT0();
        }
        __syncthreads();
        const uint32_t* Kb = Ks + buf * TKEY * 68;
        const uint32_t* Vb = Vs + buf * TKEY * 72;

        float acc[2][NT_][4];
#pragma unroll
        for (int mt = 0; mt < 2; mt++)
#pragma unroll
            for (int nt = 0; nt < NT_; nt++)
#pragma unroll
                for (int c = 0; c < 4; c++) acc[mt][nt][c] = 0.f;

#pragma unroll
        for (int ks = 0; ks < 8; ks++) {
            const int k8 = ks * 8;
            uint32_t a[2][4];
#pragma unroll
            for (int mt = 0; mt < 2; mt++) {
                int r = rowA + mt * 16;
                a[mt][0] = Qs[(r + g) * 68 + k8 + t];
                a[mt][1] = Qs[(r + g + 8) * 68 + k8 + t];
                a[mt][2] = Qs[(r + g) * 68 + k8 + t + 4];
                a[mt][3] = Qs[(r + g + 8) * 68 + k8 + t + 4];
            }
#pragma unroll
            for (int nt = 0; nt < NT_; nt++) {
                uint32_t b[2];
                b[0] = Kb[(nt * 8 + g) * 68 + k8 + t];
                b[1] = Kb[(nt * 8 + g) * 68 + k8 + t + 4];
#pragma unroll
                for (int mt = 0; mt < 2; mt++) mma_tf32(acc[mt][nt], a[mt], b);
            }
        }

        // u values + shuffle transpose per (mt, nt); V b-frags shared by mt
        const int s0 = (lane & 0x1c) | (t >> 1);
        const int s1 = s0 + 2;
        const bool odd = (t & 1);
#pragma unroll
        for (int nt = 0; nt < NT_; nt++) {
            uint32_t am[2][4];
#pragma unroll
            for (int mt = 0; mt < 2; mt++) {
                float u0 = ex2(ex2(acc[mt][nt][0] - rm[mt][0]) * zl[mt][0]);
                float u1 = ex2(ex2(acc[mt][nt][1] - rm[mt][0]) * zl[mt][0]);
                float u2 = ex2(ex2(acc[mt][nt][2] - rm[mt][1]) * zl[mt][1]);
                float u3 = ex2(ex2(acc[mt][nt][3] - rm[mt][1]) * zl[mt][1]);
                uint32_t w0 = f2tf32(u0), w1 = f2tf32(u1);
                uint32_t w2 = f2tf32(u2), w3 = f2tf32(u3);
                usum[mt][0] += __uint_as_float(w0) + __uint_as_float(w1);
                usum[mt][1] += __uint_as_float(w2) + __uint_as_float(w3);

                uint32_t d0a = __shfl_sync(0xffffffffu, w0, s0);
                uint32_t d1a = __shfl_sync(0xffffffffu, w1, s0);
                uint32_t d2a = __shfl_sync(0xffffffffu, w2, s0);
                uint32_t d3a = __shfl_sync(0xffffffffu, w3, s0);
                uint32_t d0b = __shfl_sync(0xffffffffu, w0, s1);
                uint32_t d1b = __shfl_sync(0xffffffffu, w1, s1);
                uint32_t d2b = __shfl_sync(0xffffffffu, w2, s1);
                uint32_t d3b = __shfl_sync(0xffffffffu, w3, s1);
                am[mt][0] = odd ? d1a : d0a;
                am[mt][1] = odd ? d3a : d2a;
                am[mt][2] = odd ? d1b : d0b;
                am[mt][3] = odd ? d3b : d2b;
            }
#pragma unroll
            for (int dt = 0; dt < 8; dt++) {
                uint32_t b[2];
                b[0] = Vb[(nt * 8 + t) * 72 + dt * 8 + g];
                b[1] = Vb[(nt * 8 + t + 4) * 72 + dt * 8 + g];
                mma_tf32(acco[0][dt], am[0], b);
                mma_tf32(acco[1][dt], am[1], b);
            }
        }
        __syncthreads();
    }

    // finalize: O row /= usum row
    float* O = g_O + (size_t)bh * S_ * D_;
#pragma unroll
    for (int mt = 0; mt < 2; mt++) {
        usum[mt][0] += __shfl_xor_sync(0xffffffffu, usum[mt][0], 1);
        usum[mt][0] += __shfl_xor_sync(0xffffffffu, usum[mt][0], 2);
        usum[mt][1] += __shfl_xor_sync(0xffffffffu, usum[mt][1], 1);
        usum[mt][1] += __shfl_xor_sync(0xffffffffu, usum[mt][1], 2);
        float oinv0 = 1.f / usum[mt][0];
        float oinv1 = 1.f / usum[mt][1];
        int m = m0 + rowA + mt * 16 + g;
#pragma unroll
        for (int dt = 0; dt < 8; dt++) {
            int n = dt * 8 + 2 * t;
            *(float2*)(O + (size_t)m * 64 + n) =
                make_float2(acco[mt][dt][0] * oinv0, acco[mt][dt][1] * oinv0);
            *(float2*)(O + (size_t)(m + 8) * 64 + n) =
                make_float2(acco[mt][dt][2] * oinv1, acco[mt][dt][3] * oinv1);
        }
    }
}

// ============================================================================
// Kernel 3: out projection via TF32 MMA. Y = O' @ W_out^T + b.
// NOTE: keep cvt.rna (see kernel-1 note).
// ============================================================================
__global__ __launch_bounds__(256) void out_gemm_tc(const float* __restrict__ W,
                                                   const float* __restrict__ bias,
                                                   float* __restrict__ Y) {
    __shared__ uint32_t As[128 * 36];
    __shared__ uint32_t Bs[128 * 36];
    const int tid = threadIdx.x;
    const int warp = tid >> 5, lane = tid & 31;
    const int g = lane >> 2, t = lane & 3;
    const int warpM = warp & 3;
    const int warpN = warp >> 2;
    const int m0 = blockIdx.y * 128;
    const int n0 = blockIdx.x * 128;

    float acc[2][8][4];
#pragma unroll
    for (int i = 0; i < 2; i++)
#pragma unroll
        for (int j = 0; j < 8; j++)
#pragma unroll
            for (int c = 0; c < 4; c++) acc[i][j][c] = 0.f;

    for (int kc = 0; kc < 16; kc++) {
        const int h = kc >> 1;
        const int j0 = (kc & 1) * 32;
        __syncthreads();
#pragma unroll
        for (int i = 0; i < 4; i++) {
            int idx = tid + i * 256;
            int row = idx >> 3;
            int c4 = (idx & 7) * 4;
            int mrow = m0 + row;
            int bb = mrow >> 11, s = mrow & 2047;
            float4 a = *(const float4*)(g_O + ((size_t)(bb * H_ + h) * S_ + s) * D_ + j0 + c4);
            As[row * 36 + c4 + 0] = f2tf32(a.x); As[row * 36 + c4 + 1] = f2tf32(a.y);
            As[row * 36 + c4 + 2] = f2tf32(a.z); As[row * 36 + c4 + 3] = f2tf32(a.w);
            float4 b = *(const float4*)(W + (size_t)(n0 + row) * 512 + kc * 32 + c4);
            Bs[row * 36 + c4 + 0] = f2tf32(b.x); Bs[row * 36 + c4 + 1] = f2tf32(b.y);
            Bs[row * 36 + c4 + 2] = f2tf32(b.z); Bs[row * 36 + c4 + 3] = f2tf32(b.w);
        }
        __syncthreads();
#pragma unroll
        for (int ks = 0; ks < 4; ks++) {
            const int k8 = ks * 8;
            uint32_t a[2][4];
#pragma unroll
            for (int mt = 0; mt < 2; mt++) {
                int rowA = warpM * 32 + mt * 16;
                a[mt][0] = As[(rowA + g) * 36 + k8 + t];
                a[mt][1] = As[(rowA + g + 8) * 36 + k8 + t];
                a[mt][2] = As[(rowA + g) * 36 + k8 + t + 4];
                a[mt][3] = As[(rowA + g + 8) * 36 + k8 + t + 4];
            }
#pragma unroll
            for (int nt = 0; nt < 8; nt++) {
                int colB = warpN * 64 + nt * 8;
                uint32_t b[2];
                b[0] = Bs[(colB + g) * 36 + k8 + t];
                b[1] = Bs[(colB + g) * 36 + k8 + t + 4];
#pragma unroll
                for (int mt = 0; mt < 2; mt++) mma_tf32(acc[mt][nt], a[mt], b);
            }
        }
    }

#pragma unroll
    for (int mt = 0; mt < 2; mt++) {
        int m = m0 + warpM * 32 + mt * 16 + g;
#pragma unroll
        for (int nt = 0; nt < 8; nt++) {
            int n = n0 + warpN * 64 + nt * 8 + 2 * t;
            float2 lo = {acc[mt][nt][0] + bias[n], acc[mt][nt][1] + bias[n + 1]};
            float2 hi = {acc[mt][nt][2] + bias[n], acc[mt][nt][3] + bias[n + 1]};
            *(float2*)(Y + (size_t)m * 512 + n) = lo;
            *(float2*)(Y + (size_t)(m + 8) * 512 + n) = hi;
        }
    }
}

// ============================================================================
extern "C" void kernel_launch(void* const* d_in, const int* in_sizes, int n_in,
                              void* d_out, int out_size) {
    const float* x     = (const float*)d_in[0];  // [B,S,E]
    const float* W_qkv = (const float*)d_in[1];  // [3E, E]
    const float* b_qkv = (const float*)d_in[2];  // [3E]
    const float* W_out = (const float*)d_in[3];  // [E, E]
    const float* b_out = (const float*)d_in[4];  // [E]
    float* out = (float*)d_out;                  // [B,S,E]

    cudaFuncSetAttribute(fused_attn, cudaFuncAttributeMaxDynamicSharedMemorySize,
                         FUSED_SMEM_BYTES);

    qkv_gemm_tc<<<dim3(12, 64), 256>>>(x, W_qkv, b_qkv);
    fused_attn<<<dim3(16, 32), 128, FUSED_SMEM_BYTES>>>();
    out_gemm_tc<<<dim3(4, 64), 256>>>(W_out, b_out, out);
}

// round 13
// speedup vs baseline: 3.6499x; 1.0131x over previous
#include <cuda_runtime.h>
#include <cstdint>

#define B_   4
#define S_   2048
#define E_   512
#define H_   8
#define D_   64
#define BH_  (B_ * H_)      // 32

// scale = E**-0.5; scores are DIVIDED by it => multiply by sqrt(512).
// Fused kernel folds log2(e) so softmax runs in base-2 domain.
#define SCORE_SCALE 22.62741699796952f
#define LOG2E       1.4426950408889634f
#define QSCALE_2    (SCORE_SCALE * LOG2E)

// -------------------- scratch (device globals, no allocs) --------------------
__device__ float g_Q[BH_ * S_ * D_];              // 16 MB
__device__ float g_K[BH_ * S_ * D_];              // 16 MB
__device__ float g_V[BH_ * S_ * D_];              // 16 MB
__device__ float g_O[BH_ * S_ * D_];              // 16 MB

__device__ __forceinline__ uint32_t f2tf32(float x) {
    uint32_t u;
    asm("cvt.rna.tf32.f32 %0, %1;" : "=r"(u) : "f"(x));
    return u;
}

__device__ __forceinline__ float ex2(float x) {
    float r;
    asm("ex2.approx.f32 %0, %1;" : "=f"(r) : "f"(x));
    return r;
}

__device__ __forceinline__ void mma_tf32(float* d, const uint32_t* a, const uint32_t* b) {
    asm volatile(
        "mma.sync.aligned.m16n8k8.row.col.f32.tf32.tf32.f32 "
        "{%0,%1,%2,%3},{%4,%5,%6,%7},{%8,%9},{%0,%1,%2,%3};"
        : "+f"(d[0]), "+f"(d[1]), "+f"(d[2]), "+f"(d[3])
        : "r"(a[0]), "r"(a[1]), "r"(a[2]), "r"(a[3]), "r"(b[0]), "r"(b[1]));
}

__device__ __forceinline__ void cp16(uint32_t saddr, const void* gptr) {
    asm volatile("cp.async.cg.shared.global [%0], [%1], 16;" :: "r"(saddr), "l"(gptr));
}
#define CP_COMMIT()  asm volatile("cp.async.commit_group;")
#define CP_WAIT1()   asm volatile("cp.async.wait_group 1;")
#define CP_WAIT0()   asm volatile("cp.async.wait_group 0;")

// ============================================================================
// Kernel 1: QKV projection via TF32 MMA, cp.async double-buffered.
// Raw fp32 staged in smem; cvt.rna applied at fragment load (numerics
// identical to cvt-at-store — rna happens before MMA either way).
// smem: 2 x (A 128x36 + B 128x36) fp32 = 73728 B dynamic.
// ============================================================================
#define GEMM_CHUNK_WORDS (128 * 36)                     // 4608
#define GEMM_SMEM_BYTES  (4 * GEMM_CHUNK_WORDS * 4)     // 73728

__global__ __launch_bounds__(256) void qkv_gemm_tc(const float* __restrict__ X,
                                                   const float* __restrict__ W,
                                                   const float* __restrict__ bias) {
    extern __shared__ float shg[];
    float* As = shg;                         // [2][128*36]
    float* Bs = shg + 2 * GEMM_CHUNK_WORDS;  // [2][128*36]
    const uint32_t as_base = (uint32_t)__cvta_generic_to_shared(As);
    const uint32_t bs_base = (uint32_t)__cvta_generic_to_shared(Bs);

    const int tid = threadIdx.x;
    const int warp = tid >> 5, lane = tid & 31;
    const int g = lane >> 2, t = lane & 3;
    const int warpM = warp & 3;
    const int warpN = warp >> 2;
    const int m0 = blockIdx.y * 128;
    const int n0 = blockIdx.x * 128;

    auto loadAB = [&](int kc, int buf) {
#pragma unroll
        for (int i = 0; i < 4; i++) {
            int idx = tid + i * 256;
            int row = idx >> 3;
            int c4 = (idx & 7) * 4;
            uint32_t off = (uint32_t)(buf * GEMM_CHUNK_WORDS + row * 36 + c4) * 4;
            cp16(as_base + off, X + (size_t)(m0 + row) * 512 + kc * 32 + c4);
            cp16(bs_base + off, W + (size_t)(n0 + row) * 512 + kc * 32 + c4);
        }
    };

    float acc[2][8][4];
#pragma unroll
    for (int i = 0; i < 2; i++)
#pragma unroll
        for (int j = 0; j < 8; j++)
#pragma unroll
            for (int c = 0; c < 4; c++) acc[i][j][c] = 0.f;

    loadAB(0, 0);
    CP_COMMIT();
    for (int kc = 0; kc < 16; kc++) {
        const int buf = kc & 1;
        if (kc < 15) {
            loadAB(kc + 1, buf ^ 1);
            CP_COMMIT();
            CP_WAIT1();
        } else {
            CP_WAIT0();
        }
        __syncthreads();
        const float* Ab = As + buf * GEMM_CHUNK_WORDS;
        const float* Bb = Bs + buf * GEMM_CHUNK_WORDS;
#pragma unroll
        for (int ks = 0; ks < 4; ks++) {
            const int k8 = ks * 8;
            uint32_t a[2][4];
#pragma unroll
            for (int mt = 0; mt < 2; mt++) {
                int rowA = warpM * 32 + mt * 16;
                a[mt][0] = f2tf32(Ab[(rowA + g) * 36 + k8 + t]);
                a[mt][1] = f2tf32(Ab[(rowA + g + 8) * 36 + k8 + t]);
                a[mt][2] = f2tf32(Ab[(rowA + g) * 36 + k8 + t + 4]);
                a[mt][3] = f2tf32(Ab[(rowA + g + 8) * 36 + k8 + t + 4]);
            }
#pragma unroll
            for (int nt = 0; nt < 8; nt++) {
                int colB = warpN * 64 + nt * 8;
                uint32_t b[2];
                b[0] = f2tf32(Bb[(colB + g) * 36 + k8 + t]);
                b[1] = f2tf32(Bb[(colB + g) * 36 + k8 + t + 4]);
#pragma unroll
                for (int mt = 0; mt < 2; mt++) mma_tf32(acc[mt][nt], a[mt], b);
            }
        }
        __syncthreads();
    }

#pragma unroll
    for (int mt = 0; mt < 2; mt++) {
        int m = m0 + warpM * 32 + mt * 16 + g;
        int bb = m >> 11;
        int s = m & 2047;
#pragma unroll
        for (int nt = 0; nt < 8; nt++) {
            int n = n0 + warpN * 64 + nt * 8 + 2 * t;
            int h = n / 192;
            int r = n - h * 192;
            float* dst = (r < 64) ? g_Q : (r < 128) ? g_K : g_V;
            int jj = r & 63;
            float2 lo = {acc[mt][nt][0] + bias[n], acc[mt][nt][1] + bias[n + 1]};
            float2 hi = {acc[mt][nt][2] + bias[n], acc[mt][nt][3] + bias[n + 1]};
            *(float2*)(dst + (((size_t)(bb * H_ + h) * S_ + s) * D_) + jj) = lo;
            *(float2*)(dst + (((size_t)(bb * H_ + h) * S_ + (s + 8)) * D_) + jj) = hi;
        }
    }
}

// ============================================================================
// Kernel 2: fused double-softmax attention, 2-pass flash-style, base-2 domain.
// 128 threads = 4 warps x 32 query rows (2 m-frags). 32-key tiles, cp.async
// double-buffered K/V (raw fp32 -> HW-truncated tf32).
// Q A-fragments HOISTED INTO REGISTERS for the whole kernel (64 regs) —
// staging buffer overlays the K/V smem region (dead after hoist).
// smem: K[2][32][68] + V[2][32][72] = 35840 B. __launch_bounds__(128,2)
// (256-reg cap -> no spills for the ~190-reg pass-2 live set).
// ============================================================================
#define TKEY 32
#define NT_  (TKEY / 8)          // 4 key groups per tile
#define NTILES (S_ / TKEY)       // 64 tiles
#define FUSED_SMEM_WORDS (2 * TKEY * 68 + 2 * TKEY * 72)   // 8960
#define FUSED_SMEM_BYTES (FUSED_SMEM_WORDS * 4)            // 35840
// Q staging overlay needs 128*68 = 8704 words <= 8960 ✓

__global__ __launch_bounds__(128, 2) void fused_attn() {
    extern __shared__ uint32_t sh[];
    uint32_t* Ks = sh;                       // [2][32][68]
    uint32_t* Vs = sh + 2 * TKEY * 68;       // [2][32][72]
    uint32_t* Qst = sh;                      // staging overlay (pre-pass only)

    const int tid = threadIdx.x;
    const int warp = tid >> 5, lane = tid & 31;
    const int g = lane >> 2, t = lane & 3;
    const int bh = blockIdx.y;
    const int m0 = blockIdx.x * 128;
    const int rowA = warp * 32;              // 32 rows per warp
    const float* Qp = g_Q + (size_t)bh * S_ * D_;
    const float* Kp = g_K + (size_t)bh * S_ * D_;
    const float* Vp = g_V + (size_t)bh * S_ * D_;

    const uint32_t ks_base = (uint32_t)__cvta_generic_to_shared(Ks);
    const uint32_t vs_base = (uint32_t)__cvta_generic_to_shared(Vs);

    // Stage Q (base-2 scale folded, rna) into overlay, coalesced.
#pragma unroll
    for (int i = 0; i < 16; i++) {
        int idx = tid + i * 128;
        int row = idx >> 4;
        int c4 = (idx & 15) * 4;
        float4 q = *(const float4*)(Qp + (size_t)(m0 + row) * 64 + c4);
        Qst[row * 68 + c4 + 0] = f2tf32(q.x * QSCALE_2);
        Qst[row * 68 + c4 + 1] = f2tf32(q.y * QSCALE_2);
        Qst[row * 68 + c4 + 2] = f2tf32(q.z * QSCALE_2);
        Qst[row * 68 + c4 + 3] = f2tf32(q.w * QSCALE_2);
    }
    __syncthreads();

    // Hoist this warp's Q A-fragments into registers (held both passes).
    uint32_t qa[2][8][4];
#pragma unroll
    for (int ks = 0; ks < 8; ks++) {
        const int k8 = ks * 8;
#pragma unroll
        for (int mt = 0; mt < 2; mt++) {
            int r = rowA + mt * 16;
            qa[mt][ks][0] = Qst[(r + g) * 68 + k8 + t];
            qa[mt][ks][1] = Qst[(r + g + 8) * 68 + k8 + t];
            qa[mt][ks][2] = Qst[(r + g) * 68 + k8 + t + 4];
            qa[mt][ks][3] = Qst[(r + g + 8) * 68 + k8 + t + 4];
        }
    }
    __syncthreads();   // staging dead; K/V buffers may now overwrite

    auto loadK = [&](int kt, int buf) {
#pragma unroll
        for (int i = 0; i < 4; i++) {
            int idx = tid + i * 128;
            int r = idx >> 4;
            int c4 = (idx & 15) * 4;
            cp16(ks_base + (uint32_t)((buf * TKEY + r) * 68 + c4) * 4,
                 Kp + (size_t)(kt * TKEY + r) * 64 + c4);
        }
    };
    auto loadV = [&](int kt, int buf) {
#pragma unroll
        for (int i = 0; i < 4; i++) {
            int idx = tid + i * 128;
            int r = idx >> 4;
            int c4 = (idx & 15) * 4;
            cp16(vs_base + (uint32_t)((buf * TKEY + r) * 72 + c4) * 4,
                 Vp + (size_t)(kt * TKEY + r) * 64 + c4);
        }
    };

    // stats per m-frag (mt) per row-half (h: g / g+8), base-2 domain
    float rm[2][2] = {{-3.0e38f, -3.0e38f}, {-3.0e38f, -3.0e38f}};
    float rz[2][2] = {{0.f, 0.f}, {0.f, 0.f}};

    // ----------------------------- pass 1: m, z -----------------------------
    loadK(0, 0);
    CP_COMMIT();
    for (int kt = 0; kt < NTILES; kt++) {
        const int buf = kt & 1;
        if (kt < NTILES - 1) {
            loadK(kt + 1, buf ^ 1);
            CP_COMMIT();
            CP_WAIT1();
        } else {
            CP_WAIT0();
        }
        __syncthreads();
        const uint32_t* Kb = Ks + buf * TKEY * 68;

        float acc[2][NT_][4];
#pragma unroll
        for (int mt = 0; mt < 2; mt++)
#pragma unroll
            for (int nt = 0; nt < NT_; nt++)
#pragma unroll
                for (int c = 0; c < 4; c++) acc[mt][nt][c] = 0.f;

#pragma unroll
        for (int ks = 0; ks < 8; ks++) {
            const int k8 = ks * 8;
#pragma unroll
            for (int nt = 0; nt < NT_; nt++) {
                uint32_t b[2];
                b[0] = Kb[(nt * 8 + g) * 68 + k8 + t];
                b[1] = Kb[(nt * 8 + g) * 68 + k8 + t + 4];
#pragma unroll
                for (int mt = 0; mt < 2; mt++) mma_tf32(acc[mt][nt], qa[mt][ks], b);
            }
        }

#pragma unroll
        for (int mt = 0; mt < 2; mt++) {
            float tmax[2] = {-3.0e38f, -3.0e38f};
#pragma unroll
            for (int nt = 0; nt < NT_; nt++) {
                tmax[0] = fmaxf(tmax[0], fmaxf(acc[mt][nt][0], acc[mt][nt][1]));
                tmax[1] = fmaxf(tmax[1], fmaxf(acc[mt][nt][2], acc[mt][nt][3]));
            }
#pragma unroll
            for (int h = 0; h < 2; h++) {
                tmax[h] = fmaxf(tmax[h], __shfl_xor_sync(0xffffffffu, tmax[h], 1));
                tmax[h] = fmaxf(tmax[h], __shfl_xor_sync(0xffffffffu, tmax[h], 2));
                float mnew = fmaxf(rm[mt][h], tmax[h]);
                float ts = 0.f;
#pragma unroll
                for (int nt = 0; nt < NT_; nt++) {
                    ts += ex2(acc[mt][nt][2 * h] - mnew) + ex2(acc[mt][nt][2 * h + 1] - mnew);
                }
                ts += __shfl_xor_sync(0xffffffffu, ts, 1);
                ts += __shfl_xor_sync(0xffffffffu, ts, 2);
                rz[mt][h] = rz[mt][h] * ex2(rm[mt][h] - mnew) + ts;
                rm[mt][h] = mnew;
            }
        }
        __syncthreads();
    }

    // zl = (1/z) * log2(e): u = exp(p) = 2^(p*log2e), p = 2^(s'-m') / z
    float zl[2][2];
#pragma unroll
    for (int mt = 0; mt < 2; mt++)
#pragma unroll
        for (int h = 0; h < 2; h++) zl[mt][h] = LOG2E / rz[mt][h];

    float usum[2][2] = {{0.f, 0.f}, {0.f, 0.f}};
    float acco[2][8][4];
#pragma unroll
    for (int mt = 0; mt < 2; mt++)
#pragma unroll
        for (int dt = 0; dt < 8; dt++)
#pragma unroll
            for (int c = 0; c < 4; c++) acco[mt][dt][c] = 0.f;

    // -------------------- pass 2: u = 2^(2^(s'-m')*zl); O = u@V -------------
    loadK(0, 0);
    loadV(0, 0);
    CP_COMMIT();
    for (int kt = 0; kt < NTILES; kt++) {
        const int buf = kt & 1;
        if (kt < NTILES - 1) {
            loadK(kt + 1, buf ^ 1);
            loadV(kt + 1, buf ^ 1);
            CP_COMMIT();
            CP_WAIT1();
        } else {
            CP_WAIT0();
        }
        __syncthreads();
        const uint32_t* Kb = Ks + buf * TKEY * 68;
        const uint32_t* Vb = Vs + buf * TKEY * 72;

        float acc[2][NT_][4];
#pragma unroll
        for (int mt = 0; mt < 2; mt++)
#pragma unroll
            for (int nt = 0; nt < NT_; nt++)
#pragma unroll
                for (int c = 0; c < 4; c++) acc[mt][nt][c] = 0.f;

#pragma unroll
        for (int ks = 0; ks < 8; ks++) {
            const int k8 = ks * 8;
#pragma unroll
            for (int nt = 0; nt < NT_; nt++) {
                uint32_t b[2];
                b[0] = Kb[(nt * 8 + g) * 68 + k8 + t];
                b[1] = Kb[(nt * 8 + g) * 68 + k8 + t + 4];
#pragma unroll
                for (int mt = 0; mt < 2; mt++) mma_tf32(acc[mt][nt], qa[mt][ks], b);
            }
        }

        // u values + shuffle transpose per (mt, nt); V b-frags shared by mt
        const int s0 = (lane & 0x1c) | (t >> 1);
        const int s1 = s0 + 2;
        const bool odd = (t & 1);
#pragma unroll
        for (int nt = 0; nt < NT_; nt++) {
            uint32_t am[2][4];
#pragma unroll
            for (int mt = 0; mt < 2; mt++) {
                float u0 = ex2(ex2(acc[mt][nt][0] - rm[mt][0]) * zl[mt][0]);
                float u1 = ex2(ex2(acc[mt][nt][1] - rm[mt][0]) * zl[mt][0]);
                float u2 = ex2(ex2(acc[mt][nt][2] - rm[mt][1]) * zl[mt][1]);
                float u3 = ex2(ex2(acc[mt][nt][3] - rm[mt][1]) * zl[mt][1]);
                uint32_t w0 = f2tf32(u0), w1 = f2tf32(u1);
                uint32_t w2 = f2tf32(u2), w3 = f2tf32(u3);
                usum[mt][0] += __uint_as_float(w0) + __uint_as_float(w1);
                usum[mt][1] += __uint_as_float(w2) + __uint_as_float(w3);

                uint32_t d0a = __shfl_sync(0xffffffffu, w0, s0);
                uint32_t d1a = __shfl_sync(0xffffffffu, w1, s0);
                uint32_t d2a = __shfl_sync(0xffffffffu, w2, s0);
                uint32_t d3a = __shfl_sync(0xffffffffu, w3, s0);
                uint32_t d0b = __shfl_sync(0xffffffffu, w0, s1);
                uint32_t d1b = __shfl_sync(0xffffffffu, w1, s1);
                uint32_t d2b = __shfl_sync(0xffffffffu, w2, s1);
                uint32_t d3b = __shfl_sync(0xffffffffu, w3, s1);
                am[mt][0] = odd ? d1a : d0a;
                am[mt][1] = odd ? d3a : d2a;
                am[mt][2] = odd ? d1b : d0b;
                am[mt][3] = odd ? d3b : d2b;
            }
#pragma unroll
            for (int dt = 0; dt < 8; dt++) {
                uint32_t b[2];
                b[0] = Vb[(nt * 8 + t) * 72 + dt * 8 + g];
                b[1] = Vb[(nt * 8 + t + 4) * 72 + dt * 8 + g];
                mma_tf32(acco[0][dt], am[0], b);
                mma_tf32(acco[1][dt], am[1], b);
            }
        }
        __syncthreads();
    }

    // finalize: O row /= usum row
    float* O = g_O + (size_t)bh * S_ * D_;
#pragma unroll
    for (int mt = 0; mt < 2; mt++) {
        usum[mt][0] += __shfl_xor_sync(0xffffffffu, usum[mt][0], 1);
        usum[mt][0] += __shfl_xor_sync(0xffffffffu, usum[mt][0], 2);
        usum[mt][1] += __shfl_xor_sync(0xffffffffu, usum[mt][1], 1);
        usum[mt][1] += __shfl_xor_sync(0xffffffffu, usum[mt][1], 2);
        float oinv0 = 1.f / usum[mt][0];
        float oinv1 = 1.f / usum[mt][1];
        int m = m0 + rowA + mt * 16 + g;
#pragma unroll
        for (int dt = 0; dt < 8; dt++) {
            int n = dt * 8 + 2 * t;
            *(float2*)(O + (size_t)m * 64 + n) =
                make_float2(acco[mt][dt][0] * oinv0, acco[mt][dt][1] * oinv0);
            *(float2*)(O + (size_t)(m + 8) * 64 + n) =
                make_float2(acco[mt][dt][2] * oinv1, acco[mt][dt][3] * oinv1);
        }
    }
}

// ============================================================================
// Kernel 3: out projection via TF32 MMA, cp.async double-buffered.
// Same raw-fp32-stage + cvt-at-frag-load trick as kernel 1 (rna preserved).
// ============================================================================
__global__ __launch_bounds__(256) void out_gemm_tc(const float* __restrict__ W,
                                                   const float* __restrict__ bias,
                                                   float* __restrict__ Y) {
    extern __shared__ float shg[];
    float* As = shg;
    float* Bs = shg + 2 * GEMM_CHUNK_WORDS;
    const uint32_t as_base = (uint32_t)__cvta_generic_to_shared(As);
    const uint32_t bs_base = (uint32_t)__cvta_generic_to_shared(Bs);

    const int tid = threadIdx.x;
    const int warp = tid >> 5, lane = tid & 31;
    const int g = lane >> 2, t = lane & 3;
    const int warpM = warp & 3;
    const int warpN = warp >> 2;
    const int m0 = blockIdx.y * 128;
    const int n0 = blockIdx.x * 128;

    auto loadAB = [&](int kc, int buf) {
        const int h = kc >> 1;
        const int j0 = (kc & 1) * 32;
#pragma unroll
        for (int i = 0; i < 4; i++) {
            int idx = tid + i * 256;
            int row = idx >> 3;
            int c4 = (idx & 7) * 4;
            uint32_t off = (uint32_t)(buf * GEMM_CHUNK_WORDS + row * 36 + c4) * 4;
            int mrow = m0 + row;
            int bb = mrow >> 11, s = mrow & 2047;
            cp16(as_base + off,
                 g_O + ((size_t)(bb * H_ + h) * S_ + s) * D_ + j0 + c4);
            cp16(bs_base + off, W + (size_t)(n0 + row) * 512 + kc * 32 + c4);
        }
    };

    float acc[2][8][4];
#pragma unroll
    for (int i = 0; i < 2; i++)
#pragma unroll
        for (int j = 0; j < 8; j++)
#pragma unroll
            for (int c = 0; c < 4; c++) acc[i][j][c] = 0.f;

    loadAB(0, 0);
    CP_COMMIT();
    for (int kc = 0; kc < 16; kc++) {
        const int buf = kc & 1;
        if (kc < 15) {
            loadAB(kc + 1, buf ^ 1);
            CP_COMMIT();
            CP_WAIT1();
        } else {
            CP_WAIT0();
        }
        __syncthreads();
        const float* Ab = As + buf * GEMM_CHUNK_WORDS;
        const float* Bb = Bs + buf * GEMM_CHUNK_WORDS;
#pragma unroll
        for (int ks = 0; ks < 4; ks++) {
            const int k8 = ks * 8;
            uint32_t a[2][4];
#pragma unroll
            for (int mt = 0; mt < 2; mt++) {
                int rowA = warpM * 32 + mt * 16;
                a[mt][0] = f2tf32(Ab[(rowA + g) * 36 + k8 + t]);
                a[mt][1] = f2tf32(Ab[(rowA + g + 8) * 36 + k8 + t]);
                a[mt][2] = f2tf32(Ab[(rowA + g) * 36 + k8 + t + 4]);
                a[mt][3] = f2tf32(Ab[(rowA + g + 8) * 36 + k8 + t + 4]);
            }
#pragma unroll
            for (int nt = 0; nt < 8; nt++) {
                int colB = warpN * 64 + nt * 8;
                uint32_t b[2];
                b[0] = f2tf32(Bb[(colB + g) * 36 + k8 + t]);
                b[1] = f2tf32(Bb[(colB + g) * 36 + k8 + t + 4]);
#pragma unroll
                for (int mt = 0; mt < 2; mt++) mma_tf32(acc[mt][nt], a[mt], b);
            }
        }
        __syncthreads();
    }

#pragma unroll
    for (int mt = 0; mt < 2; mt++) {
        int m = m0 + warpM * 32 + mt * 16 + g;
#pragma unroll
        for (int nt = 0; nt < 8; nt++) {
            int n = n0 + warpN * 64 + nt * 8 + 2 * t;
            float2 lo = {acc[mt][nt][0] + bias[n], acc[mt][nt][1] + bias[n + 1]};
            float2 hi = {acc[mt][nt][2] + bias[n], acc[mt][nt][3] + bias[n + 1]};
            *(float2*)(Y + (size_t)m * 512 + n) = lo;
            *(float2*)(Y + (size_t)(m + 8) * 512 + n) = hi;
        }
    }
}

// ============================================================================
extern "C" void kernel_launch(void* const* d_in, const int* in_sizes, int n_in,
                              void* d_out, int out_size) {
    const float* x     = (const float*)d_in[0];  // [B,S,E]
    const float* W_qkv = (const float*)d_in[1];  // [3E, E]
    const float* b_qkv = (const float*)d_in[2];  // [3E]
    const float* W_out = (const float*)d_in[3];  // [E, E]
    const float* b_out = (const float*)d_in[4];  // [E]
    float* out = (float*)d_out;                  // [B,S,E]

    cudaFuncSetAttribute(qkv_gemm_tc, cudaFuncAttributeMaxDynamicSharedMemorySize,
                         GEMM_SMEM_BYTES);
    cudaFuncSetAttribute(out_gemm_tc, cudaFuncAttributeMaxDynamicSharedMemorySize,
                         GEMM_SMEM_BYTES);
    cudaFuncSetAttribute(fused_attn, cudaFuncAttributeMaxDynamicSharedMemorySize,
                         FUSED_SMEM_BYTES);

    qkv_gemm_tc<<<dim3(12, 64), 256, GEMM_SMEM_BYTES>>>(x, W_qkv, b_qkv);
    fused_attn<<<dim3(16, 32), 128, FUSED_SMEM_BYTES>>>();
    out_gemm_tc<<<dim3(4, 64), 256, GEMM_SMEM_BYTES>>>(W_out, b_out, out);
}

// round 14
// speedup vs baseline: 3.8150x; 1.0452x over previous
#include <cuda_runtime.h>
#include <cstdint>

#define B_   4
#define S_   2048
#define E_   512
#define H_   8
#define D_   64
#define BH_  (B_ * H_)      // 32

#define SCORE_SCALE 22.62741699796952f
#define LOG2E       1.4426950408889634f
#define QSCALE_2    (SCORE_SCALE * LOG2E)

// g_K layout: [bh][s][72], k-pair-permuted within each 8-chunk:
//   store_col(k) = (k&~7) | ((k&3)<<1) | ((k&7)>>2)  (k, k+4 adjacent)
// g_V layout: [bh][tile=s/32][2176], addr = (nt*4+t)*136 + d*2 + p
//   where k=s%32, nt=k>>3, t=(k&7)&3, p=(k&7)>>2.
#define KROW  72
#define VTILE 2176

// -------------------- scratch (device globals, no allocs) --------------------
__device__ float g_Q[BH_ * S_ * D_];                 // 16 MB
__device__ float g_K[(size_t)BH_ * S_ * KROW];       // 18.9 MB
__device__ float g_V[(size_t)BH_ * (S_ / 32) * VTILE]; // 17.8 MB
__device__ float g_O[BH_ * S_ * D_];                 // 16 MB

__device__ __forceinline__ uint32_t f2tf32(float x) {
    uint32_t u;
    asm("cvt.rna.tf32.f32 %0, %1;" : "=r"(u) : "f"(x));
    return u;
}

__device__ __forceinline__ float ex2(float x) {
    float r;
    asm("ex2.approx.f32 %0, %1;" : "=f"(r) : "f"(x));
    return r;
}

__device__ __forceinline__ void mma_tf32(float* d, const uint32_t* a, const uint32_t* b) {
    asm volatile(
        "mma.sync.aligned.m16n8k8.row.col.f32.tf32.tf32.f32 "
        "{%0,%1,%2,%3},{%4,%5,%6,%7},{%8,%9},{%0,%1,%2,%3};"
        : "+f"(d[0]), "+f"(d[1]), "+f"(d[2]), "+f"(d[3])
        : "r"(a[0]), "r"(a[1]), "r"(a[2]), "r"(a[3]), "r"(b[0]), "r"(b[1]));
}

__device__ __forceinline__ void cp16(uint32_t saddr, const void* gptr) {
    asm volatile("cp.async.cg.shared.global [%0], [%1], 16;" :: "r"(saddr), "l"(gptr));
}
#define CP_COMMIT()  asm volatile("cp.async.commit_group;")
#define CP_WAIT1()   asm volatile("cp.async.wait_group 1;")
#define CP_WAIT0()   asm volatile("cp.async.wait_group 0;")

__device__ __forceinline__ int kperm(int j) {
    return (j & ~7) | ((j & 3) << 1) | ((j & 7) >> 2);
}

// ============================================================================
// Kernel 1: QKV projection via TF32 MMA, cp.async double-buffered.
// Epilogue scatters into permuted g_K / g_V layouts (values unchanged).
// ============================================================================
#define GEMM_CHUNK_WORDS (128 * 36)                     // 4608
#define GEMM_SMEM_BYTES  (4 * GEMM_CHUNK_WORDS * 4)     // 73728

__global__ __launch_bounds__(256) void qkv_gemm_tc(const float* __restrict__ X,
                                                   const float* __restrict__ W,
                                                   const float* __restrict__ bias) {
    extern __shared__ float shg[];
    float* As = shg;
    float* Bs = shg + 2 * GEMM_CHUNK_WORDS;
    const uint32_t as_base = (uint32_t)__cvta_generic_to_shared(As);
    const uint32_t bs_base = (uint32_t)__cvta_generic_to_shared(Bs);

    const int tid = threadIdx.x;
    const int warp = tid >> 5, lane = tid & 31;
    const int g = lane >> 2, t = lane & 3;
    const int warpM = warp & 3;
    const int warpN = warp >> 2;
    const int m0 = blockIdx.y * 128;
    const int n0 = blockIdx.x * 128;

    auto loadAB = [&](int kc, int buf) {
#pragma unroll
        for (int i = 0; i < 4; i++) {
            int idx = tid + i * 256;
            int row = idx >> 3;
            int c4 = (idx & 7) * 4;
            uint32_t off = (uint32_t)(buf * GEMM_CHUNK_WORDS + row * 36 + c4) * 4;
            cp16(as_base + off, X + (size_t)(m0 + row) * 512 + kc * 32 + c4);
            cp16(bs_base + off, W + (size_t)(n0 + row) * 512 + kc * 32 + c4);
        }
    };

    float acc[2][8][4];
#pragma unroll
    for (int i = 0; i < 2; i++)
#pragma unroll
        for (int j = 0; j < 8; j++)
#pragma unroll
            for (int c = 0; c < 4; c++) acc[i][j][c] = 0.f;

    loadAB(0, 0);
    CP_COMMIT();
    for (int kc = 0; kc < 16; kc++) {
        const int buf = kc & 1;
        if (kc < 15) {
            loadAB(kc + 1, buf ^ 1);
            CP_COMMIT();
            CP_WAIT1();
        } else {
            CP_WAIT0();
        }
        __syncthreads();
        const float* Ab = As + buf * GEMM_CHUNK_WORDS;
        const float* Bb = Bs + buf * GEMM_CHUNK_WORDS;
#pragma unroll
        for (int ks = 0; ks < 4; ks++) {
            const int k8 = ks * 8;
            uint32_t a[2][4];
#pragma unroll
            for (int mt = 0; mt < 2; mt++) {
                int rowA = warpM * 32 + mt * 16;
                a[mt][0] = f2tf32(Ab[(rowA + g) * 36 + k8 + t]);
                a[mt][1] = f2tf32(Ab[(rowA + g + 8) * 36 + k8 + t]);
                a[mt][2] = f2tf32(Ab[(rowA + g) * 36 + k8 + t + 4]);
                a[mt][3] = f2tf32(Ab[(rowA + g + 8) * 36 + k8 + t + 4]);
            }
#pragma unroll
            for (int nt = 0; nt < 8; nt++) {
                int colB = warpN * 64 + nt * 8;
                uint32_t b[2];
                b[0] = f2tf32(Bb[(colB + g) * 36 + k8 + t]);
                b[1] = f2tf32(Bb[(colB + g) * 36 + k8 + t + 4]);
#pragma unroll
                for (int mt = 0; mt < 2; mt++) mma_tf32(acc[mt][nt], a[mt], b);
            }
        }
        __syncthreads();
    }

#pragma unroll
    for (int mt = 0; mt < 2; mt++) {
        int m = m0 + warpM * 32 + mt * 16 + g;
        int bb = m >> 11;
        int s = m & 2047;
#pragma unroll
        for (int nt = 0; nt < 8; nt++) {
            int n = n0 + warpN * 64 + nt * 8 + 2 * t;
            int h = n / 192;
            int r = n - h * 192;
            int bh = bb * H_ + h;
            float v0l = acc[mt][nt][0] + bias[n];
            float v1l = acc[mt][nt][1] + bias[n + 1];
            float v0h = acc[mt][nt][2] + bias[n];
            float v1h = acc[mt][nt][3] + bias[n + 1];
            int jj = r & 63;
            if (r < 64) {          // Q: plain [bh][s][64]
                float* dq = g_Q + (((size_t)bh * S_ + s) * D_) + jj;
                *(float2*)dq = make_float2(v0l, v1l);
                *(float2*)(dq + 8 * D_) = make_float2(v0h, v1h);
            } else if (r < 128) {  // K: [bh][s][72] k-permuted
                float* dk = g_K + ((size_t)bh * S_ + s) * KROW;
                dk[kperm(jj)] = v0l;
                dk[kperm(jj + 1)] = v1l;
                float* dk2 = dk + (size_t)8 * KROW;
                dk2[kperm(jj)] = v0h;
                dk2[kperm(jj + 1)] = v1h;
            } else {               // V: [bh][tile][2176] pair-interleaved
                auto vaddr = [&](int ss, int j) -> size_t {
                    int k = ss & 31;
                    int nt2 = k >> 3, tq = k & 7;
                    return (size_t)bh * (S_ / 32) * VTILE + (size_t)(ss >> 5) * VTILE
                         + (size_t)((nt2 * 4 + (tq & 3)) * 136) + j * 2 + (tq >> 2);
                };
                g_V[vaddr(s, jj)] = v0l;
                g_V[vaddr(s, jj + 1)] = v1l;
                g_V[vaddr(s + 8, jj)] = v0h;
                g_V[vaddr(s + 8, jj + 1)] = v1h;
            }
        }
    }
}

// ============================================================================
// Kernel 2: fused double-softmax attention, 2-pass flash-style, base-2 domain.
// 128 thr = 4 warps x 32 rows. 32-key tiles, cp.async double-buffered K/V.
// Q A-frags hoisted to registers. B-fragments loaded as single LDS.64 via
// permuted K (pair-adjacent, stride 72) and V (row-pair interleaved, 136).
// smem: K[2][32][72] + V[2][2176] = 8960 words = 35840 B. occ 2.
// ============================================================================
#define TKEY 32
#define NT_  (TKEY / 8)
#define NTILES (S_ / TKEY)
#define FUSED_SMEM_WORDS (2 * TKEY * KROW + 2 * VTILE)   // 8960
#define FUSED_SMEM_BYTES (FUSED_SMEM_WORDS * 4)          // 35840
// Q staging overlay: 128*68 = 8704 <= 8960 ✓

__global__ __launch_bounds__(128, 2) void fused_attn() {
    extern __shared__ uint32_t sh[];
    uint32_t* Ks = sh;                       // [2][32][72]
    uint32_t* Vs = sh + 2 * TKEY * KROW;     // [2][2176]
    uint32_t* Qst = sh;                      // staging overlay

    const int tid = threadIdx.x;
    const int warp = tid >> 5, lane = tid & 31;
    const int g = lane >> 2, t = lane & 3;
    const int bh = blockIdx.y;
    const int m0 = blockIdx.x * 128;
    const int rowA = warp * 32;
    const float* Qp = g_Q + (size_t)bh * S_ * D_;
    const float* Kp = g_K + (size_t)bh * S_ * KROW;
    const float* Vp = g_V + (size_t)bh * (S_ / 32) * VTILE;

    const uint32_t ks_base = (uint32_t)__cvta_generic_to_shared(Ks);
    const uint32_t vs_base = (uint32_t)__cvta_generic_to_shared(Vs);

    // Stage Q (base-2 scale folded, rna), then hoist fragments.
#pragma unroll
    for (int i = 0; i < 16; i++) {
        int idx = tid + i * 128;
        int row = idx >> 4;
        int c4 = (idx & 15) * 4;
        float4 q = *(const float4*)(Qp + (size_t)(m0 + row) * 64 + c4);
        Qst[row * 68 + c4 + 0] = f2tf32(q.x * QSCALE_2);
        Qst[row * 68 + c4 + 1] = f2tf32(q.y * QSCALE_2);
        Qst[row * 68 + c4 + 2] = f2tf32(q.z * QSCALE_2);
        Qst[row * 68 + c4 + 3] = f2tf32(q.w * QSCALE_2);
    }
    __syncthreads();

    uint32_t qa[2][8][4];
#pragma unroll
    for (int ks = 0; ks < 8; ks++) {
        const int k8 = ks * 8;
#pragma unroll
        for (int mt = 0; mt < 2; mt++) {
            int r = rowA + mt * 16;
            qa[mt][ks][0] = Qst[(r + g) * 68 + k8 + t];
            qa[mt][ks][1] = Qst[(r + g + 8) * 68 + k8 + t];
            qa[mt][ks][2] = Qst[(r + g) * 68 + k8 + t + 4];
            qa[mt][ks][3] = Qst[(r + g + 8) * 68 + k8 + t + 4];
        }
    }
    __syncthreads();

    auto loadK = [&](int kt, int buf) {
#pragma unroll
        for (int i = 0; i < 4; i++) {
            int idx = tid + i * 128;
            int r = idx >> 4;
            int c4 = (idx & 15) * 4;
            cp16(ks_base + (uint32_t)((buf * TKEY + r) * KROW + c4) * 4,
                 Kp + (size_t)(kt * TKEY + r) * KROW + c4);
        }
    };
    auto loadV = [&](int kt, int buf) {
#pragma unroll
        for (int i = 0; i < 5; i++) {
            int idx = tid + i * 128;      // float4 index, 544 total
            if (idx < VTILE / 4) {
                cp16(vs_base + (uint32_t)(buf * VTILE + idx * 4) * 4,
                     Vp + (size_t)kt * VTILE + idx * 4);
            }
        }
    };

    float rm[2][2] = {{-3.0e38f, -3.0e38f}, {-3.0e38f, -3.0e38f}};
    float rz[2][2] = {{0.f, 0.f}, {0.f, 0.f}};

    // ----------------------------- pass 1: m, z -----------------------------
    loadK(0, 0);
    CP_COMMIT();
    for (int kt = 0; kt < NTILES; kt++) {
        const int buf = kt & 1;
        if (kt < NTILES - 1) {
            loadK(kt + 1, buf ^ 1);
            CP_COMMIT();
            CP_WAIT1();
        } else {
            CP_WAIT0();
        }
        __syncthreads();
        const uint32_t* Kb = Ks + buf * TKEY * KROW;

        float acc[2][NT_][4];
#pragma unroll
        for (int mt = 0; mt < 2; mt++)
#pragma unroll
            for (int nt = 0; nt < NT_; nt++)
#pragma unroll
                for (int c = 0; c < 4; c++) acc[mt][nt][c] = 0.f;

#pragma unroll
        for (int ks = 0; ks < 8; ks++) {
            const int k8 = ks * 8;
#pragma unroll
            for (int nt = 0; nt < NT_; nt++) {
                uint2 kv = *(const uint2*)&Kb[(nt * 8 + g) * KROW + k8 + 2 * t];
                uint32_t b[2] = {kv.x, kv.y};   // logical k8+t, k8+t+4
#pragma unroll
                for (int mt = 0; mt < 2; mt++) mma_tf32(acc[mt][nt], qa[mt][ks], b);
            }
        }

#pragma unroll
        for (int mt = 0; mt < 2; mt++) {
            float tmax[2] = {-3.0e38f, -3.0e38f};
#pragma unroll
            for (int nt = 0; nt < NT_; nt++) {
                tmax[0] = fmaxf(tmax[0], fmaxf(acc[mt][nt][0], acc[mt][nt][1]));
                tmax[1] = fmaxf(tmax[1], fmaxf(acc[mt][nt][2], acc[mt][nt][3]));
            }
#pragma unroll
            for (int h = 0; h < 2; h++) {
                tmax[h] = fmaxf(tmax[h], __shfl_xor_sync(0xffffffffu, tmax[h], 1));
                tmax[h] = fmaxf(tmax[h], __shfl_xor_sync(0xffffffffu, tmax[h], 2));
                float mnew = fmaxf(rm[mt][h], tmax[h]);
                float ts = 0.f;
#pragma unroll
                for (int nt = 0; nt < NT_; nt++) {
                    ts += ex2(acc[mt][nt][2 * h] - mnew) + ex2(acc[mt][nt][2 * h + 1] - mnew);
                }
                ts += __shfl_xor_sync(0xffffffffu, ts, 1);
                ts += __shfl_xor_sync(0xffffffffu, ts, 2);
                rz[mt][h] = rz[mt][h] * ex2(rm[mt][h] - mnew) + ts;
                rm[mt][h] = mnew;
            }
        }
        __syncthreads();
    }

    float zl[2][2];
#pragma unroll
    for (int mt = 0; mt < 2; mt++)
#pragma unroll
        for (int h = 0; h < 2; h++) zl[mt][h] = LOG2E / rz[mt][h];

    float usum[2][2] = {{0.f, 0.f}, {0.f, 0.f}};
    float acco[2][8][4];
#pragma unroll
    for (int mt = 0; mt < 2; mt++)
#pragma unroll
        for (int dt = 0; dt < 8; dt++)
#pragma unroll
            for (int c = 0; c < 4; c++) acco[mt][dt][c] = 0.f;

    // -------------------- pass 2: u = 2^(2^(s'-m')*zl); O = u@V -------------
    loadK(0, 0);
    loadV(0, 0);
    CP_COMMIT();
    for (int kt = 0; kt < NTILES; kt++) {
        const int buf = kt & 1;
        if (kt < NTILES - 1) {
            loadK(kt + 1, buf ^ 1);
            loadV(kt + 1, buf ^ 1);
            CP_COMMIT();
            CP_WAIT1();
        } else {
            CP_WAIT0();
        }
        __syncthreads();
        const uint32_t* Kb = Ks + buf * TKEY * KROW;
        const uint32_t* Vb = Vs + buf * VTILE;

        float acc[2][NT_][4];
#pragma unroll
        for (int mt = 0; mt < 2; mt++)
#pragma unroll
            for (int nt = 0; nt < NT_; nt++)
#pragma unroll
                for (int c = 0; c < 4; c++) acc[mt][nt][c] = 0.f;

#pragma unroll
        for (int ks = 0; ks < 8; ks++) {
            const int k8 = ks * 8;
#pragma unroll
            for (int nt = 0; nt < NT_; nt++) {
                uint2 kv = *(const uint2*)&Kb[(nt * 8 + g) * KROW + k8 + 2 * t];
                uint32_t b[2] = {kv.x, kv.y};
#pragma unroll
                for (int mt = 0; mt < 2; mt++) mma_tf32(acc[mt][nt], qa[mt][ks], b);
            }
        }

        const int s0 = (lane & 0x1c) | (t >> 1);
        const int s1 = s0 + 2;
        const bool odd = (t & 1);
#pragma unroll
        for (int nt = 0; nt < NT_; nt++) {
            uint32_t am[2][4];
#pragma unroll
            for (int mt = 0; mt < 2; mt++) {
                float u0 = ex2(ex2(acc[mt][nt][0] - rm[mt][0]) * zl[mt][0]);
                float u1 = ex2(ex2(acc[mt][nt][1] - rm[mt][0]) * zl[mt][0]);
                float u2 = ex2(ex2(acc[mt][nt][2] - rm[mt][1]) * zl[mt][1]);
                float u3 = ex2(ex2(acc[mt][nt][3] - rm[mt][1]) * zl[mt][1]);
                uint32_t w0 = f2tf32(u0), w1 = f2tf32(u1);
                uint32_t w2 = f2tf32(u2), w3 = f2tf32(u3);
                usum[mt][0] += __uint_as_float(w0) + __uint_as_float(w1);
                usum[mt][1] += __uint_as_float(w2) + __uint_as_float(w3);

                uint32_t d0a = __shfl_sync(0xffffffffu, w0, s0);
                uint32_t d1a = __shfl_sync(0xffffffffu, w1, s0);
                uint32_t d2a = __shfl_sync(0xffffffffu, w2, s0);
                uint32_t d3a = __shfl_sync(0xffffffffu, w3, s0);
                uint32_t d0b = __shfl_sync(0xffffffffu, w0, s1);
                uint32_t d1b = __shfl_sync(0xffffffffu, w1, s1);
                uint32_t d2b = __shfl_sync(0xffffffffu, w2, s1);
                uint32_t d3b = __shfl_sync(0xffffffffu, w3, s1);
                am[mt][0] = odd ? d1a : d0a;
                am[mt][1] = odd ? d3a : d2a;
                am[mt][2] = odd ? d1b : d0b;
                am[mt][3] = odd ? d3b : d2b;
            }
#pragma unroll
            for (int dt = 0; dt < 8; dt++) {
                uint2 vv = *(const uint2*)&Vb[(nt * 4 + t) * 136 + (dt * 8 + g) * 2];
                uint32_t b[2] = {vv.x, vv.y};   // rows nt*8+t, nt*8+t+4
                mma_tf32(acco[0][dt], am[0], b);
                mma_tf32(acco[1][dt], am[1], b);
            }
        }
        __syncthreads();
    }

    float* O = g_O + (size_t)bh * S_ * D_;
#pragma unroll
    for (int mt = 0; mt < 2; mt++) {
        usum[mt][0] += __shfl_xor_sync(0xffffffffu, usum[mt][0], 1);
        usum[mt][0] += __shfl_xor_sync(0xffffffffu, usum[mt][0], 2);
        usum[mt][1] += __shfl_xor_sync(0xffffffffu, usum[mt][1], 1);
        usum[mt][1] += __shfl_xor_sync(0xffffffffu, usum[mt][1], 2);
        float oinv0 = 1.f / usum[mt][0];
        float oinv1 = 1.f / usum[mt][1];
        int m = m0 + rowA + mt * 16 + g;
#pragma unroll
        for (int dt = 0; dt < 8; dt++) {
            int n = dt * 8 + 2 * t;
            *(float2*)(O + (size_t)m * 64 + n) =
                make_float2(acco[mt][dt][0] * oinv0, acco[mt][dt][1] * oinv0);
            *(float2*)(O + (size_t)(m + 8) * 64 + n) =
                make_float2(acco[mt][dt][2] * oinv1, acco[mt][dt][3] * oinv1);
        }
    }
}

// ============================================================================
// Kernel 3: out projection via TF32 MMA, cp.async double-buffered (unchanged).
// ============================================================================
__global__ __launch_bounds__(256) void out_gemm_tc(const float* __restrict__ W,
                                                   const float* __restrict__ bias,
                                                   float* __restrict__ Y) {
    extern __shared__ float shg[];
    float* As = shg;
    float* Bs = shg + 2 * GEMM_CHUNK_WORDS;
    const uint32_t as_base = (uint32_t)__cvta_generic_to_shared(As);
    const uint32_t bs_base = (uint32_t)__cvta_generic_to_shared(Bs);

    const int tid = threadIdx.x;
    const int warp = tid >> 5, lane = tid & 31;
    const int g = lane >> 2, t = lane & 3;
    const int warpM = warp & 3;
    const int warpN = warp >> 2;
    const int m0 = blockIdx.y * 128;
    const int n0 = blockIdx.x * 128;

    auto loadAB = [&](int kc, int buf) {
        const int h = kc >> 1;
        const int j0 = (kc & 1) * 32;
#pragma unroll
        for (int i = 0; i < 4; i++) {
            int idx = tid + i * 256;
            int row = idx >> 3;
            int c4 = (idx & 7) * 4;
            uint32_t off = (uint32_t)(buf * GEMM_CHUNK_WORDS + row * 36 + c4) * 4;
            int mrow = m0 + row;
            int bb = mrow >> 11, s = mrow & 2047;
            cp16(as_base + off,
                 g_O + ((size_t)(bb * H_ + h) * S_ + s) * D_ + j0 + c4);
            cp16(bs_base + off, W + (size_t)(n0 + row) * 512 + kc * 32 + c4);
        }
    };

    float acc[2][8][4];
#pragma unroll
    for (int i = 0; i < 2; i++)
#pragma unroll
        for (int j = 0; j < 8; j++)
#pragma unroll
            for (int c = 0; c < 4; c++) acc[i][j][c] = 0.f;

    loadAB(0, 0);
    CP_COMMIT();
    for (int kc = 0; kc < 16; kc++) {
        const int buf = kc & 1;
        if (kc < 15) {
            loadAB(kc + 1, buf ^ 1);
            CP_COMMIT();
            CP_WAIT1();
        } else {
            CP_WAIT0();
        }
        __syncthreads();
        const float* Ab = As + buf * GEMM_CHUNK_WORDS;
        const float* Bb = Bs + buf * GEMM_CHUNK_WORDS;
#pragma unroll
        for (int ks = 0; ks < 4; ks++) {
            const int k8 = ks * 8;
            uint32_t a[2][4];
#pragma unroll
            for (int mt = 0; mt < 2; mt++) {
                int rowA = warpM * 32 + mt * 16;
                a[mt][0] = f2tf32(Ab[(rowA + g) * 36 + k8 + t]);
                a[mt][1] = f2tf32(Ab[(rowA + g + 8) * 36 + k8 + t]);
                a[mt][2] = f2tf32(Ab[(rowA + g) * 36 + k8 + t + 4]);
                a[mt][3] = f2tf32(Ab[(rowA + g + 8) * 36 + k8 + t + 4]);
            }
#pragma unroll
            for (int nt = 0; nt < 8; nt++) {
                int colB = warpN * 64 + nt * 8;
                uint32_t b[2];
                b[0] = f2tf32(Bb[(colB + g) * 36 + k8 + t]);
                b[1] = f2tf32(Bb[(colB + g) * 36 + k8 + t + 4]);
#pragma unroll
                for (int mt = 0; mt < 2; mt++) mma_tf32(acc[mt][nt], a[mt], b);
            }
        }
        __syncthreads();
    }

#pragma unroll
    for (int mt = 0; mt < 2; mt++) {
        int m = m0 + warpM * 32 + mt * 16 + g;
#pragma unroll
        for (int nt = 0; nt < 8; nt++) {
            int n = n0 + warpN * 64 + nt * 8 + 2 * t;
            float2 lo = {acc[mt][nt][0] + bias[n], acc[mt][nt][1] + bias[n + 1]};
            float2 hi = {acc[mt][nt][2] + bias[n], acc[mt][nt][3] + bias[n + 1]};
            *(float2*)(Y + (size_t)m * 512 + n) = lo;
            *(float2*)(Y + (size_t)(m + 8) * 512 + n) = hi;
        }
    }
}

// ============================================================================
extern "C" void kernel_launch(void* const* d_in, const int* in_sizes, int n_in,
                              void* d_out, int out_size) {
    const float* x     = (const float*)d_in[0];
    const float* W_qkv = (const float*)d_in[1];
    const float* b_qkv = (const float*)d_in[2];
    const float* W_out = (const float*)d_in[3];
    const float* b_out = (const float*)d_in[4];
    float* out = (float*)d_out;

    cudaFuncSetAttribute(qkv_gemm_tc, cudaFuncAttributeMaxDynamicSharedMemorySize,
                         GEMM_SMEM_BYTES);
    cudaFuncSetAttribute(out_gemm_tc, cudaFuncAttributeMaxDynamicSharedMemorySize,
                         GEMM_SMEM_BYTES);
    cudaFuncSetAttribute(fused_attn, cudaFuncAttributeMaxDynamicSharedMemorySize,
                         FUSED_SMEM_BYTES);

    qkv_gemm_tc<<<dim3(12, 64), 256, GEMM_SMEM_BYTES>>>(x, W_qkv, b_qkv);
    fused_attn<<<dim3(16, 32), 128, FUSED_SMEM_BYTES>>>();
    out_gemm_tc<<<dim3(4, 64), 256, GEMM_SMEM_BYTES>>>(W_out, b_out, out);
}